// round 2
// baseline (speedup 1.0000x reference)
#include <cuda_runtime.h>
#include <math.h>

#define NH   16
#define HD   64
#define NB   2
#define SEQ  2048
#define DM   1024
#define MTOT (NB*SEQ)

// Scratch (allocation-free rule: __device__ globals)
__device__ float g_Q[(size_t)NB*NH*SEQ*HD];
__device__ float g_K[(size_t)NB*NH*SEQ*HD];
__device__ float g_V[(size_t)NB*NH*SEQ*HD];
__device__ float g_C[(size_t)MTOT*DM];

// ---------------------------------------------------------------------------
// GEMM: Out = A[M,K] @ W[N,K]^T + bias   (M=4096, N=K=1024)
// SRC: 0 = param Ain (x), 1 = g_C (context)
// DST: 0/1/2 = g_Q/g_K/g_V in [B,H,S,hd] layout, 3 = param Out row-major
// Tiles: 64x64 block, BK=16, 256 threads, 4x4 per-thread microtile.
// ---------------------------------------------------------------------------
template<int SRC, int DST>
__global__ __launch_bounds__(256) void gemm_kernel(const float* __restrict__ Ain,
                                                   const float* __restrict__ W,
                                                   const float* __restrict__ bias,
                                                   float* __restrict__ Out)
{
    const float* A = (SRC == 0) ? Ain : g_C;
    __shared__ float As[16][64];
    __shared__ float Ws[16][64];
    const int tid = threadIdx.x;
    const int bm = blockIdx.y * 64;
    const int bn = blockIdx.x * 64;
    const int tx = tid & 15, ty = tid >> 4;
    const int lr = tid >> 2;          // 0..63: tile row
    const int lc = (tid & 3) << 2;    // 0,4,8,12: k offset

    float acc[4][4];
    #pragma unroll
    for (int i = 0; i < 4; i++)
        #pragma unroll
        for (int j = 0; j < 4; j++) acc[i][j] = 0.f;

    const float* Aptr = A + (size_t)(bm + lr) * DM + lc;
    const float* Wptr = W + (size_t)(bn + lr) * DM + lc;

    for (int k0 = 0; k0 < DM; k0 += 16) {
        float4 a4 = *(const float4*)(Aptr + k0);
        float4 w4 = *(const float4*)(Wptr + k0);
        As[lc+0][lr] = a4.x; As[lc+1][lr] = a4.y; As[lc+2][lr] = a4.z; As[lc+3][lr] = a4.w;
        Ws[lc+0][lr] = w4.x; Ws[lc+1][lr] = w4.y; Ws[lc+2][lr] = w4.z; Ws[lc+3][lr] = w4.w;
        __syncthreads();
        #pragma unroll
        for (int k = 0; k < 16; k++) {
            float4 av = *(const float4*)&As[k][ty*4];
            float4 wv = *(const float4*)&Ws[k][tx*4];
            float a[4] = {av.x, av.y, av.z, av.w};
            float w[4] = {wv.x, wv.y, wv.z, wv.w};
            #pragma unroll
            for (int i = 0; i < 4; i++)
                #pragma unroll
                for (int j = 0; j < 4; j++)
                    acc[i][j] = fmaf(a[i], w[j], acc[i][j]);
        }
        __syncthreads();
    }

    #pragma unroll
    for (int i = 0; i < 4; i++) {
        const int m = bm + ty*4 + i;
        #pragma unroll
        for (int j = 0; j < 4; j++) {
            const int n = bn + tx*4 + j;
            float v = acc[i][j] + bias[n];
            if (DST <= 2) {
                float* O = (DST == 0) ? g_Q : (DST == 1) ? g_K : g_V;
                const int b = m >> 11, s = m & (SEQ - 1);
                const int h = n >> 6, d = n & (HD - 1);
                O[((size_t)(b*NH + h)*SEQ + s)*HD + d] = v;
            } else {
                Out[(size_t)m*DM + n] = v;
            }
        }
    }
}

// ---------------------------------------------------------------------------
// Flash-style masked attention. 1 thread = 1 query row (hd=64 ctx in regs).
// Block = 64 threads (64 queries), grid = (S/64, B*H).
// K/V tiles 64x64 fp32 in smem; mask staged as 32-bit WORDS (one per element,
// nonzero = keep; works for float32 1.0f and int32 1 encodings alike).
// Online softmax with deferred rescale (only on new running max).
// Writes ctx directly in [B,S,H*hd] layout into g_C.
// ---------------------------------------------------------------------------
__global__ __launch_bounds__(64) void attn_kernel(const unsigned int* __restrict__ maskw)
{
    __shared__ float Ks[64*64];
    __shared__ float Vs[64*64];
    __shared__ unsigned int Ms[64*65];   // [row][65] padded: conflict-free row reads

    const int tid = threadIdx.x;
    const int bh  = blockIdx.y;               // b*NH + h
    const int q0  = blockIdx.x * 64;
    const int q   = q0 + tid;                 // query index within sequence
    const float scale = 0.125f;               // 1/sqrt(64)

    // Load Q row into registers
    float qreg[64];
    const float* Qp = g_Q + ((size_t)bh*SEQ + q)*HD;
    #pragma unroll
    for (int i = 0; i < 16; i++) {
        float4 t = *(const float4*)(Qp + i*4);
        qreg[i*4+0] = t.x; qreg[i*4+1] = t.y; qreg[i*4+2] = t.z; qreg[i*4+3] = t.w;
    }

    float ctx[64];
    #pragma unroll
    for (int d = 0; d < 64; d++) ctx[d] = 0.f;
    float mrun = -INFINITY;
    float lsum = 0.f;

    const float* Kbase = g_K + (size_t)bh*SEQ*HD;
    const float* Vbase = g_V + (size_t)bh*SEQ*HD;
    const unsigned int* Mbase = maskw + ((size_t)bh*SEQ + q0)*SEQ;  // tile's first mask row

    for (int kt = 0; kt < SEQ/64; kt++) {
        __syncthreads();   // previous tile fully consumed
        // Cooperative K/V tile load (fully coalesced float4)
        const float* Kt = Kbase + kt*64*HD;
        const float* Vt = Vbase + kt*64*HD;
        #pragma unroll
        for (int i = 0; i < 16; i++) {
            const int idx = i*256 + tid*4;
            *(float4*)&Ks[idx] = *(const float4*)(Kt + idx);
            *(float4*)&Vs[idx] = *(const float4*)(Vt + idx);
        }
        // Mask tile [64 q-rows][64 k-words], coalesced: row r, thread tid loads word tid
        const unsigned int* Mt = Mbase + kt*64;
        #pragma unroll 8
        for (int r = 0; r < 64; r++) {
            Ms[r*65 + tid] = Mt[(size_t)r*SEQ + tid];
        }
        __syncthreads();

        const unsigned int* myMask = &Ms[tid*65];
        for (int j = 0; j < 64; j++) {
            if (myMask[j] == 0u) continue;

            const float4* kp = (const float4*)&Ks[j*64];
            float s0 = 0.f, s1 = 0.f, s2 = 0.f, s3 = 0.f;
            #pragma unroll
            for (int i = 0; i < 16; i++) {
                float4 kv = kp[i];
                s0 = fmaf(qreg[i*4+0], kv.x, s0);
                s1 = fmaf(qreg[i*4+1], kv.y, s1);
                s2 = fmaf(qreg[i*4+2], kv.z, s2);
                s3 = fmaf(qreg[i*4+3], kv.w, s3);
            }
            const float s = ((s0 + s1) + (s2 + s3)) * scale;

            if (s > mrun) {                       // rare after warmup (~ln S times)
                const float corr = __expf(mrun - s);   // exp(-inf)=0 on first hit
                mrun = s;
                lsum *= corr;
                #pragma unroll
                for (int d = 0; d < 64; d++) ctx[d] *= corr;
            }
            const float p = __expf(s - mrun);
            lsum += p;
            const float4* vp = (const float4*)&Vs[j*64];
            #pragma unroll
            for (int i = 0; i < 16; i++) {
                float4 vv = vp[i];
                ctx[i*4+0] = fmaf(p, vv.x, ctx[i*4+0]);
                ctx[i*4+1] = fmaf(p, vv.y, ctx[i*4+1]);
                ctx[i*4+2] = fmaf(p, vv.z, ctx[i*4+2]);
                ctx[i*4+3] = fmaf(p, vv.w, ctx[i*4+3]);
            }
        }
    }

    // Fully-masked row -> lsum==0 -> output 0 (matches nan_to_num)
    const float inv = (lsum > 0.f) ? 1.f / lsum : 0.f;
    const int b = bh >> 4, h = bh & (NH - 1);
    float* Op = g_C + ((size_t)(b*SEQ + q))*DM + h*HD;
    #pragma unroll
    for (int i = 0; i < 16; i++) {
        float4 o;
        o.x = ctx[i*4+0]*inv; o.y = ctx[i*4+1]*inv;
        o.z = ctx[i*4+2]*inv; o.w = ctx[i*4+3]*inv;
        *(float4*)(Op + i*4) = o;
    }
}

// ---------------------------------------------------------------------------
// Inputs (metadata order): x, keep_mask, Wq, bq, Wk, bk, Wv, bv, Wo, bo
// ---------------------------------------------------------------------------
extern "C" void kernel_launch(void* const* d_in, const int* in_sizes, int n_in,
                              void* d_out, int out_size)
{
    const float* x    = (const float*)d_in[0];
    const unsigned int* maskw = (const unsigned int*)d_in[1];  // 32-bit per element
    const float* Wq = (const float*)d_in[2];
    const float* bq = (const float*)d_in[3];
    const float* Wk = (const float*)d_in[4];
    const float* bk = (const float*)d_in[5];
    const float* Wv = (const float*)d_in[6];
    const float* bv = (const float*)d_in[7];
    const float* Wo = (const float*)d_in[8];
    const float* bo = (const float*)d_in[9];
    float* out = (float*)d_out;

    dim3 ggrid(DM/64, MTOT/64);   // (16, 64)
    gemm_kernel<0,0><<<ggrid, 256>>>(x, Wq, bq, nullptr);
    gemm_kernel<0,1><<<ggrid, 256>>>(x, Wk, bk, nullptr);
    gemm_kernel<0,2><<<ggrid, 256>>>(x, Wv, bv, nullptr);

    dim3 agrid(SEQ/64, NB*NH);    // (32, 32)
    attn_kernel<<<agrid, 64>>>(maskw);

    gemm_kernel<1,3><<<ggrid, 256>>>(nullptr, Wo, bo, out);
}

// round 4
// speedup vs baseline: 1.3006x; 1.3006x over previous
#include <cuda_runtime.h>
#include <cuda_bf16.h>
#include <math.h>
#include <stdint.h>

#define NH   16
#define HD   64
#define NB   2
#define SEQ  2048
#define DM   1024
#define MTOT (NB*SEQ)

// ---------------- device scratch (allocation-free rule) ----------------
__device__ float g_Q[(size_t)NB*NH*SEQ*HD];
__device__ float g_K[(size_t)NB*NH*SEQ*HD];
__device__ float g_V[(size_t)NB*NH*SEQ*HD];
__device__ float g_C[(size_t)MTOT*DM];

__device__ __nv_bfloat16 g_xh[(size_t)MTOT*DM], g_xl[(size_t)MTOT*DM];
__device__ __nv_bfloat16 g_ch[(size_t)MTOT*DM], g_cl[(size_t)MTOT*DM];
__device__ __nv_bfloat16 g_wqh[(size_t)DM*DM], g_wql[(size_t)DM*DM];
__device__ __nv_bfloat16 g_wkh[(size_t)DM*DM], g_wkl[(size_t)DM*DM];
__device__ __nv_bfloat16 g_wvh[(size_t)DM*DM], g_wvl[(size_t)DM*DM];
__device__ __nv_bfloat16 g_woh[(size_t)DM*DM], g_wol[(size_t)DM*DM];

// ---------------- helpers ----------------
__device__ __forceinline__ uint32_t smem_u32(const void* p) {
    uint32_t a;
    asm("{ .reg .u64 t; cvta.to.shared.u64 t, %1; cvt.u32.u64 %0, t; }" : "=r"(a) : "l"(p));
    return a;
}
// byte-offset swizzle for 64B rows: chunk ^= (row>>1)&3
__device__ __forceinline__ uint32_t sw64(uint32_t o) {
    return o ^ (((o >> 7) & 3u) << 4);
}
__device__ __forceinline__ void ldsm_x4(uint32_t a, uint32_t& r0, uint32_t& r1,
                                        uint32_t& r2, uint32_t& r3) {
    asm volatile("ldmatrix.sync.aligned.m8n8.x4.shared.b16 {%0,%1,%2,%3}, [%4];"
                 : "=r"(r0), "=r"(r1), "=r"(r2), "=r"(r3) : "r"(a));
}
__device__ __forceinline__ void mma16816(float* c, uint32_t a0, uint32_t a1,
                                         uint32_t a2, uint32_t a3,
                                         uint32_t b0, uint32_t b1) {
    asm volatile(
        "mma.sync.aligned.m16n8k16.row.col.f32.bf16.bf16.f32 "
        "{%0,%1,%2,%3}, {%4,%5,%6,%7}, {%8,%9}, {%0,%1,%2,%3};"
        : "+f"(c[0]), "+f"(c[1]), "+f"(c[2]), "+f"(c[3])
        : "r"(a0), "r"(a1), "r"(a2), "r"(a3), "r"(b0), "r"(b1));
}

// ---------------- convert fp32 -> bf16 hi/lo pair ----------------
__global__ __launch_bounds__(256) void conv_hilo(const float4* __restrict__ src,
                                                 __nv_bfloat162* __restrict__ hi,
                                                 __nv_bfloat162* __restrict__ lo,
                                                 int n4) {
    int i = blockIdx.x * 256 + threadIdx.x;
    if (i >= n4) return;
    float4 v = src[i];
    __nv_bfloat16 hx = __float2bfloat16(v.x), hy = __float2bfloat16(v.y);
    __nv_bfloat16 hz = __float2bfloat16(v.z), hw = __float2bfloat16(v.w);
    __nv_bfloat162 h01; h01.x = hx; h01.y = hy;
    __nv_bfloat162 h23; h23.x = hz; h23.y = hw;
    __nv_bfloat162 l01, l23;
    l01.x = __float2bfloat16(v.x - __bfloat162float(hx));
    l01.y = __float2bfloat16(v.y - __bfloat162float(hy));
    l23.x = __float2bfloat16(v.z - __bfloat162float(hz));
    l23.y = __float2bfloat16(v.w - __bfloat162float(hw));
    hi[2*i]   = h01; hi[2*i+1] = h23;
    lo[2*i]   = l01; lo[2*i+1] = l23;
}

// ---------------- mma.sync bf16 GEMM: Out[M,N] = A[M,K]@B[N,K]^T + bias ----
// CTA tile 128x128, 8 warps (warp tile 32x64), BK=32, hi/lo 3-term split.
// DST: 0/1/2 scatter to g_Q/g_K/g_V in [B,H,S,hd]; 3 -> row-major Out.
template<int DST>
__global__ __launch_bounds__(256, 1)
void gemm_tc(const __nv_bfloat16* __restrict__ Ahi, const __nv_bfloat16* __restrict__ Alo,
             const __nv_bfloat16* __restrict__ Bhi, const __nv_bfloat16* __restrict__ Blo,
             const float* __restrict__ bias, float* __restrict__ Out)
{
    __shared__ char smb[4 * 8192];   // Ah, Al, Bh, Bl tiles (128x32 bf16 each)
    const uint32_t sb = smem_u32(smb);
    const uint32_t sAh = sb, sAl = sb + 8192, sBh = sb + 16384, sBl = sb + 24576;

    const int tid = threadIdx.x;
    const int wid = tid >> 5;
    const int lid = tid & 31;
    const int wm = wid & 3;          // warp m index (rows wm*32..+31)
    const int wn = wid >> 2;         // warp n index (cols wn*64..+63)
    const int bm = blockIdx.y * 128;
    const int bn = blockIdx.x * 128;

    float acc[2][8][4];
    #pragma unroll
    for (int mi = 0; mi < 2; mi++)
        #pragma unroll
        for (int ni = 0; ni < 8; ni++)
            #pragma unroll
            for (int e = 0; e < 4; e++) acc[mi][ni][e] = 0.f;

    // tile-fill indexing: thread -> (row, 16B chunk)
    const int fr = tid >> 2;         // 0..63
    const int fc = tid & 3;          // chunk in row

    for (int c = 0; c < DM / 32; c++) {
        __syncthreads();
        #pragma unroll
        for (int p = 0; p < 2; p++) {
            const int r = fr + p * 64;
            const uint32_t so = sw64((uint32_t)(r * 64 + fc * 16));
            const size_t ga = (size_t)(bm + r) * (DM / 8) + c * 4 + fc;  // uint4 units
            const size_t gb = (size_t)(bn + r) * (DM / 8) + c * 4 + fc;
            *(uint4*)(smb + 0     + so) = ((const uint4*)Ahi)[ga];
            *(uint4*)(smb + 8192  + so) = ((const uint4*)Alo)[ga];
            *(uint4*)(smb + 16384 + so) = ((const uint4*)Bhi)[gb];
            *(uint4*)(smb + 24576 + so) = ((const uint4*)Blo)[gb];
        }
        __syncthreads();

        #pragma unroll
        for (int ks = 0; ks < 2; ks++) {
            // ---- A fragments (hi & lo), mi = 0,1 ----
            uint32_t ah[2][4], al[2][4];
            #pragma unroll
            for (int mi = 0; mi < 2; mi++) {
                const int row = wm * 32 + mi * 16 + (lid & 15);
                const int colb = (ks * 16 + (lid >> 4) * 8) * 2;
                const uint32_t off = sw64((uint32_t)(row * 64 + colb));
                ldsm_x4(sAh + off, ah[mi][0], ah[mi][1], ah[mi][2], ah[mi][3]);
                ldsm_x4(sAl + off, al[mi][0], al[mi][1], al[mi][2], al[mi][3]);
            }
            // ---- B fragments (hi & lo), ni = 0..7 in pairs ----
            uint32_t bh[8][2], bl[8][2];
            #pragma unroll
            for (int nj = 0; nj < 4; nj++) {
                const int row = wn * 64 + nj * 16 + ((lid >> 4) << 3) + (lid & 7);
                const int colb = (ks * 16 + ((lid >> 3) & 1) * 8) * 2;
                const uint32_t off = sw64((uint32_t)(row * 64 + colb));
                uint32_t r0, r1, r2, r3;
                ldsm_x4(sBh + off, r0, r1, r2, r3);
                bh[nj*2][0] = r0; bh[nj*2][1] = r1; bh[nj*2+1][0] = r2; bh[nj*2+1][1] = r3;
                ldsm_x4(sBl + off, r0, r1, r2, r3);
                bl[nj*2][0] = r0; bl[nj*2][1] = r1; bl[nj*2+1][0] = r2; bl[nj*2+1][1] = r3;
            }
            // ---- MMAs: AhBh + AhBl + AlBh ----
            #pragma unroll
            for (int mi = 0; mi < 2; mi++)
                #pragma unroll
                for (int ni = 0; ni < 8; ni++) {
                    mma16816(acc[mi][ni], ah[mi][0], ah[mi][1], ah[mi][2], ah[mi][3],
                             bh[ni][0], bh[ni][1]);
                    mma16816(acc[mi][ni], ah[mi][0], ah[mi][1], ah[mi][2], ah[mi][3],
                             bl[ni][0], bl[ni][1]);
                    mma16816(acc[mi][ni], al[mi][0], al[mi][1], al[mi][2], al[mi][3],
                             bh[ni][0], bh[ni][1]);
                }
        }
    }

    // ---- epilogue: c0,c1 -> row m, c2,c3 -> row m+8; cols ni*8 + (lid&3)*2 ----
    const int qr = lid >> 2, qc = lid & 3;
    #pragma unroll
    for (int mi = 0; mi < 2; mi++) {
        #pragma unroll
        for (int half = 0; half < 2; half++) {
            const int m = bm + wm * 32 + mi * 16 + half * 8 + qr;
            float* dst;
            int dbase;
            if (DST <= 2) {
                float* O = (DST == 0) ? g_Q : (DST == 1) ? g_K : g_V;
                const int b = m >> 11, s = m & (SEQ - 1);
                const int n0 = bn + wn * 64;
                const int h = n0 >> 6;
                dst = O + ((size_t)(b * NH + h) * SEQ + s) * HD;
                dbase = 0;
            } else {
                dst = Out + (size_t)m * DM;
                dbase = bn + wn * 64;
            }
            #pragma unroll
            for (int ni = 0; ni < 8; ni++) {
                const int nloc = ni * 8 + qc * 2;
                const int nglob = bn + wn * 64 + nloc;
                float2 o;
                o.x = acc[mi][ni][half*2+0] + bias[nglob];
                o.y = acc[mi][ni][half*2+1] + bias[nglob + 1];
                *(float2*)(dst + dbase + ((DST <= 2) ? nloc : nloc)) = o;
            }
        }
    }
}

// ---------------- SIMT masked attention (unchanged from passing R2) --------
__global__ __launch_bounds__(64) void attn_kernel(const unsigned int* __restrict__ maskw)
{
    __shared__ float Ks[64*64];
    __shared__ float Vs[64*64];
    __shared__ unsigned int Ms[64*65];

    const int tid = threadIdx.x;
    const int bh  = blockIdx.y;
    const int q0  = blockIdx.x * 64;
    const int q   = q0 + tid;
    const float scale = 0.125f;

    float qreg[64];
    const float* Qp = g_Q + ((size_t)bh*SEQ + q)*HD;
    #pragma unroll
    for (int i = 0; i < 16; i++) {
        float4 t = *(const float4*)(Qp + i*4);
        qreg[i*4+0] = t.x; qreg[i*4+1] = t.y; qreg[i*4+2] = t.z; qreg[i*4+3] = t.w;
    }

    float ctx[64];
    #pragma unroll
    for (int d = 0; d < 64; d++) ctx[d] = 0.f;
    float mrun = -INFINITY;
    float lsum = 0.f;

    const float* Kbase = g_K + (size_t)bh*SEQ*HD;
    const float* Vbase = g_V + (size_t)bh*SEQ*HD;
    const unsigned int* Mbase = maskw + ((size_t)bh*SEQ + q0)*SEQ;

    for (int kt = 0; kt < SEQ/64; kt++) {
        __syncthreads();
        const float* Kt = Kbase + kt*64*HD;
        const float* Vt = Vbase + kt*64*HD;
        #pragma unroll
        for (int i = 0; i < 16; i++) {
            const int idx = i*256 + tid*4;
            *(float4*)&Ks[idx] = *(const float4*)(Kt + idx);
            *(float4*)&Vs[idx] = *(const float4*)(Vt + idx);
        }
        const unsigned int* Mt = Mbase + kt*64;
        #pragma unroll 8
        for (int r = 0; r < 64; r++) {
            Ms[r*65 + tid] = Mt[(size_t)r*SEQ + tid];
        }
        __syncthreads();

        const unsigned int* myMask = &Ms[tid*65];
        for (int j = 0; j < 64; j++) {
            if (myMask[j] == 0u) continue;

            const float4* kp = (const float4*)&Ks[j*64];
            float s0 = 0.f, s1 = 0.f, s2 = 0.f, s3 = 0.f;
            #pragma unroll
            for (int i = 0; i < 16; i++) {
                float4 kv = kp[i];
                s0 = fmaf(qreg[i*4+0], kv.x, s0);
                s1 = fmaf(qreg[i*4+1], kv.y, s1);
                s2 = fmaf(qreg[i*4+2], kv.z, s2);
                s3 = fmaf(qreg[i*4+3], kv.w, s3);
            }
            const float s = ((s0 + s1) + (s2 + s3)) * scale;

            if (s > mrun) {
                const float corr = __expf(mrun - s);
                mrun = s;
                lsum *= corr;
                #pragma unroll
                for (int d = 0; d < 64; d++) ctx[d] *= corr;
            }
            const float p = __expf(s - mrun);
            lsum += p;
            const float4* vp = (const float4*)&Vs[j*64];
            #pragma unroll
            for (int i = 0; i < 16; i++) {
                float4 vv = vp[i];
                ctx[i*4+0] = fmaf(p, vv.x, ctx[i*4+0]);
                ctx[i*4+1] = fmaf(p, vv.y, ctx[i*4+1]);
                ctx[i*4+2] = fmaf(p, vv.z, ctx[i*4+2]);
                ctx[i*4+3] = fmaf(p, vv.w, ctx[i*4+3]);
            }
        }
    }

    const float inv = (lsum > 0.f) ? 1.f / lsum : 0.f;
    const int b = bh >> 4, h = bh & (NH - 1);
    float* Op = g_C + ((size_t)(b*SEQ + q))*DM + h*HD;
    #pragma unroll
    for (int i = 0; i < 16; i++) {
        float4 o;
        o.x = ctx[i*4+0]*inv; o.y = ctx[i*4+1]*inv;
        o.z = ctx[i*4+2]*inv; o.w = ctx[i*4+3]*inv;
        *(float4*)(Op + i*4) = o;
    }
}

// ---------------- launch ----------------
extern "C" void kernel_launch(void* const* d_in, const int* in_sizes, int n_in,
                              void* d_out, int out_size)
{
    const float* x  = (const float*)d_in[0];
    const unsigned int* maskw = (const unsigned int*)d_in[1];
    const float* Wq = (const float*)d_in[2];
    const float* bq = (const float*)d_in[3];
    const float* Wk = (const float*)d_in[4];
    const float* bk = (const float*)d_in[5];
    const float* Wv = (const float*)d_in[6];
    const float* bv = (const float*)d_in[7];
    const float* Wo = (const float*)d_in[8];
    const float* bo = (const float*)d_in[9];
    float* out = (float*)d_out;

    __nv_bfloat16 *xh, *xl, *ch, *cl, *wqh, *wql, *wkh, *wkl, *wvh, *wvl, *woh, *wol;
    cudaGetSymbolAddress((void**)&xh,  g_xh);  cudaGetSymbolAddress((void**)&xl,  g_xl);
    cudaGetSymbolAddress((void**)&ch,  g_ch);  cudaGetSymbolAddress((void**)&cl,  g_cl);
    cudaGetSymbolAddress((void**)&wqh, g_wqh); cudaGetSymbolAddress((void**)&wql, g_wql);
    cudaGetSymbolAddress((void**)&wkh, g_wkh); cudaGetSymbolAddress((void**)&wkl, g_wkl);
    cudaGetSymbolAddress((void**)&wvh, g_wvh); cudaGetSymbolAddress((void**)&wvl, g_wvl);
    cudaGetSymbolAddress((void**)&woh, g_woh); cudaGetSymbolAddress((void**)&wol, g_wol);
    float* cbuf; cudaGetSymbolAddress((void**)&cbuf, g_C);

    const int nx4 = (int)((size_t)MTOT * DM / 4);
    const int nw4 = (int)((size_t)DM * DM / 4);
    conv_hilo<<<nx4/256, 256>>>((const float4*)x,  (__nv_bfloat162*)xh,  (__nv_bfloat162*)xl,  nx4);
    conv_hilo<<<nw4/256, 256>>>((const float4*)Wq, (__nv_bfloat162*)wqh, (__nv_bfloat162*)wql, nw4);
    conv_hilo<<<nw4/256, 256>>>((const float4*)Wk, (__nv_bfloat162*)wkh, (__nv_bfloat162*)wkl, nw4);
    conv_hilo<<<nw4/256, 256>>>((const float4*)Wv, (__nv_bfloat162*)wvh, (__nv_bfloat162*)wvl, nw4);
    conv_hilo<<<nw4/256, 256>>>((const float4*)Wo, (__nv_bfloat162*)woh, (__nv_bfloat162*)wol, nw4);

    dim3 ggrid(DM / 128, MTOT / 128);   // (8, 32)
    gemm_tc<0><<<ggrid, 256>>>(xh, xl, wqh, wql, bq, nullptr);
    gemm_tc<1><<<ggrid, 256>>>(xh, xl, wkh, wkl, bk, nullptr);
    gemm_tc<2><<<ggrid, 256>>>(xh, xl, wvh, wvl, bv, nullptr);

    dim3 agrid(SEQ / 64, NB * NH);      // (32, 32)
    attn_kernel<<<agrid, 64>>>(maskw);

    conv_hilo<<<nx4/256, 256>>>((const float4*)cbuf, (__nv_bfloat162*)ch, (__nv_bfloat162*)cl, nx4);
    gemm_tc<3><<<ggrid, 256>>>(ch, cl, woh, wol, bo, out);
}

// round 5
// speedup vs baseline: 2.4959x; 1.9191x over previous
#include <cuda_runtime.h>
#include <cuda_bf16.h>
#include <math.h>
#include <stdint.h>

#define NH   16
#define HD   64
#define NB   2
#define SEQ  2048
#define DM   1024
#define MTOT (NB*SEQ)

// ---------------- device scratch (allocation-free rule) ----------------
__device__ __nv_bfloat16 g_Qh[(size_t)NB*NH*SEQ*HD], g_Ql[(size_t)NB*NH*SEQ*HD];
__device__ __nv_bfloat16 g_Kh[(size_t)NB*NH*SEQ*HD], g_Kl[(size_t)NB*NH*SEQ*HD];
__device__ __nv_bfloat16 g_Vh[(size_t)NB*NH*SEQ*HD], g_Vl[(size_t)NB*NH*SEQ*HD];
__device__ __nv_bfloat16 g_xh[(size_t)MTOT*DM], g_xl[(size_t)MTOT*DM];
__device__ __nv_bfloat16 g_ch[(size_t)MTOT*DM], g_cl[(size_t)MTOT*DM];
__device__ __nv_bfloat16 g_wqh[(size_t)DM*DM], g_wql[(size_t)DM*DM];
__device__ __nv_bfloat16 g_wkh[(size_t)DM*DM], g_wkl[(size_t)DM*DM];
__device__ __nv_bfloat16 g_wvh[(size_t)DM*DM], g_wvl[(size_t)DM*DM];
__device__ __nv_bfloat16 g_woh[(size_t)DM*DM], g_wol[(size_t)DM*DM];

// ---------------- helpers ----------------
__device__ __forceinline__ uint32_t smem_u32(const void* p) {
    uint32_t a;
    asm("{ .reg .u64 t; cvta.to.shared.u64 t, %1; cvt.u32.u64 %0, t; }" : "=r"(a) : "l"(p));
    return a;
}
// swizzle for 128B rows: 16B-chunk ^= row&7
__device__ __forceinline__ uint32_t sw128(uint32_t o) {
    return o ^ (((o >> 7) & 7u) << 4);
}
// swizzle for 64B rows (GEMM tiles)
__device__ __forceinline__ uint32_t sw64(uint32_t o) {
    return o ^ (((o >> 7) & 3u) << 4);
}
__device__ __forceinline__ void ldsm_x4(uint32_t a, uint32_t* r) {
    asm volatile("ldmatrix.sync.aligned.m8n8.x4.shared.b16 {%0,%1,%2,%3}, [%4];"
                 : "=r"(r[0]), "=r"(r[1]), "=r"(r[2]), "=r"(r[3]) : "r"(a));
}
__device__ __forceinline__ void ldsm_x4t(uint32_t a, uint32_t* r) {
    asm volatile("ldmatrix.sync.aligned.m8n8.x4.trans.shared.b16 {%0,%1,%2,%3}, [%4];"
                 : "=r"(r[0]), "=r"(r[1]), "=r"(r[2]), "=r"(r[3]) : "r"(a));
}
__device__ __forceinline__ void mma16816(float* c, const uint32_t* a,
                                         uint32_t b0, uint32_t b1) {
    asm volatile(
        "mma.sync.aligned.m16n8k16.row.col.f32.bf16.bf16.f32 "
        "{%0,%1,%2,%3}, {%4,%5,%6,%7}, {%8,%9}, {%0,%1,%2,%3};"
        : "+f"(c[0]), "+f"(c[1]), "+f"(c[2]), "+f"(c[3])
        : "r"(a[0]), "r"(a[1]), "r"(a[2]), "r"(a[3]), "r"(b0), "r"(b1));
}
// fast exp: input e = x*log2(e); FMA-only (no MUFU). |e| <= ~8 in practice.
__device__ __forceinline__ float fexp2(float e) {
    float t = e + 12582912.0f;                 // round-to-nearest int via magic
    int   ib = __float_as_int(t);
    float r = t - 12582912.0f;
    float f = e - r;                           // f in [-0.5, 0.5]
    float p = 1.3333558e-3f;
    p = fmaf(p, f, 9.6181291e-3f);
    p = fmaf(p, f, 5.5504109e-2f);
    p = fmaf(p, f, 2.4022651e-1f);
    p = fmaf(p, f, 6.9314718e-1f);
    p = fmaf(p, f, 1.0f);
    return __int_as_float((ib + (127 - 0x4B400000)) << 23) * p;
}
__device__ __forceinline__ uint32_t packbf(float lo, float hi) {
    uint32_t r;
    asm("cvt.rn.bf16x2.f32 %0, %1, %2;" : "=r"(r) : "f"(hi), "f"(lo));
    return r;
}

// ---------------- convert fp32 -> bf16 hi/lo pair ----------------
__global__ __launch_bounds__(256) void conv_hilo(const float4* __restrict__ src,
                                                 __nv_bfloat162* __restrict__ hi,
                                                 __nv_bfloat162* __restrict__ lo,
                                                 int n4) {
    int i = blockIdx.x * 256 + threadIdx.x;
    if (i >= n4) return;
    float4 v = src[i];
    __nv_bfloat16 hx = __float2bfloat16(v.x), hy = __float2bfloat16(v.y);
    __nv_bfloat16 hz = __float2bfloat16(v.z), hw = __float2bfloat16(v.w);
    __nv_bfloat162 h01; h01.x = hx; h01.y = hy;
    __nv_bfloat162 h23; h23.x = hz; h23.y = hw;
    __nv_bfloat162 l01, l23;
    l01.x = __float2bfloat16(v.x - __bfloat162float(hx));
    l01.y = __float2bfloat16(v.y - __bfloat162float(hy));
    l23.x = __float2bfloat16(v.z - __bfloat162float(hz));
    l23.y = __float2bfloat16(v.w - __bfloat162float(hw));
    hi[2*i]   = h01; hi[2*i+1] = h23;
    lo[2*i]   = l01; lo[2*i+1] = l23;
}

// ---------------- mma.sync bf16 GEMM ----------------
// Out[M,N] = A[M,K]@B[N,K]^T + bias.  CTA 128x128, 8 warps, BK=32, 3-term hi/lo.
// DST 0/1/2: write bf16 hi/lo to OutH/OutL in [b,h,s,d]; DST 3: fp32 row-major.
template<int DST>
__global__ __launch_bounds__(256, 1)
void gemm_tc(const __nv_bfloat16* __restrict__ Ahi, const __nv_bfloat16* __restrict__ Alo,
             const __nv_bfloat16* __restrict__ Bhi, const __nv_bfloat16* __restrict__ Blo,
             const float* __restrict__ bias,
             __nv_bfloat16* __restrict__ OutH, __nv_bfloat16* __restrict__ OutL,
             float* __restrict__ Out)
{
    __shared__ char smb[4 * 8192];
    const uint32_t sb = smem_u32(smb);
    const uint32_t sAh = sb, sAl = sb + 8192, sBh = sb + 16384, sBl = sb + 24576;

    const int tid = threadIdx.x;
    const int wid = tid >> 5;
    const int lid = tid & 31;
    const int wm = wid & 3;
    const int wn = wid >> 2;
    const int bm = blockIdx.y * 128;
    const int bn = blockIdx.x * 128;

    float acc[2][8][4];
    #pragma unroll
    for (int mi = 0; mi < 2; mi++)
        #pragma unroll
        for (int ni = 0; ni < 8; ni++)
            #pragma unroll
            for (int e = 0; e < 4; e++) acc[mi][ni][e] = 0.f;

    const int fr = tid >> 2;
    const int fc = tid & 3;

    for (int c = 0; c < DM / 32; c++) {
        __syncthreads();
        #pragma unroll
        for (int p = 0; p < 2; p++) {
            const int r = fr + p * 64;
            const uint32_t so = sw64((uint32_t)(r * 64 + fc * 16));
            const size_t ga = (size_t)(bm + r) * (DM / 8) + c * 4 + fc;
            const size_t gb = (size_t)(bn + r) * (DM / 8) + c * 4 + fc;
            *(uint4*)(smb + 0     + so) = ((const uint4*)Ahi)[ga];
            *(uint4*)(smb + 8192  + so) = ((const uint4*)Alo)[ga];
            *(uint4*)(smb + 16384 + so) = ((const uint4*)Bhi)[gb];
            *(uint4*)(smb + 24576 + so) = ((const uint4*)Blo)[gb];
        }
        __syncthreads();

        #pragma unroll
        for (int ks = 0; ks < 2; ks++) {
            uint32_t ah[2][4], al[2][4];
            #pragma unroll
            for (int mi = 0; mi < 2; mi++) {
                const int row = wm * 32 + mi * 16 + (lid & 15);
                const int colb = (ks * 16 + (lid >> 4) * 8) * 2;
                const uint32_t off = sw64((uint32_t)(row * 64 + colb));
                ldsm_x4(sAh + off, ah[mi]);
                ldsm_x4(sAl + off, al[mi]);
            }
            uint32_t bh[8][2], bl[8][2];
            #pragma unroll
            for (int nj = 0; nj < 4; nj++) {
                const int row = wn * 64 + nj * 16 + ((lid >> 4) << 3) + (lid & 7);
                const int colb = (ks * 16 + ((lid >> 3) & 1) * 8) * 2;
                const uint32_t off = sw64((uint32_t)(row * 64 + colb));
                uint32_t t[4];
                ldsm_x4(sBh + off, t);
                bh[nj*2][0] = t[0]; bh[nj*2][1] = t[1];
                bh[nj*2+1][0] = t[2]; bh[nj*2+1][1] = t[3];
                ldsm_x4(sBl + off, t);
                bl[nj*2][0] = t[0]; bl[nj*2][1] = t[1];
                bl[nj*2+1][0] = t[2]; bl[nj*2+1][1] = t[3];
            }
            #pragma unroll
            for (int mi = 0; mi < 2; mi++)
                #pragma unroll
                for (int ni = 0; ni < 8; ni++) {
                    mma16816(acc[mi][ni], ah[mi], bh[ni][0], bh[ni][1]);
                    mma16816(acc[mi][ni], ah[mi], bl[ni][0], bl[ni][1]);
                    mma16816(acc[mi][ni], al[mi], bh[ni][0], bh[ni][1]);
                }
        }
    }

    const int qr = lid >> 2, qc = lid & 3;
    #pragma unroll
    for (int mi = 0; mi < 2; mi++) {
        #pragma unroll
        for (int half = 0; half < 2; half++) {
            const int m = bm + wm * 32 + mi * 16 + half * 8 + qr;
            const int n0 = bn + wn * 64;
            if (DST <= 2) {
                const int b = m >> 11, s = m & (SEQ - 1);
                const int h = n0 >> 6;
                const size_t base = ((size_t)(b * NH + h) * SEQ + s) * HD;
                #pragma unroll
                for (int ni = 0; ni < 8; ni++) {
                    const int nloc = ni * 8 + qc * 2;
                    const int ng = n0 + nloc;
                    float v0 = acc[mi][ni][half*2+0] + bias[ng];
                    float v1 = acc[mi][ni][half*2+1] + bias[ng + 1];
                    __nv_bfloat16 h0 = __float2bfloat16(v0);
                    __nv_bfloat16 h1 = __float2bfloat16(v1);
                    __nv_bfloat162 hh; hh.x = h0; hh.y = h1;
                    __nv_bfloat162 ll;
                    ll.x = __float2bfloat16(v0 - __bfloat162float(h0));
                    ll.y = __float2bfloat16(v1 - __bfloat162float(h1));
                    *(__nv_bfloat162*)(OutH + base + nloc) = hh;
                    *(__nv_bfloat162*)(OutL + base + nloc) = ll;
                }
            } else {
                float* dst = Out + (size_t)m * DM;
                #pragma unroll
                for (int ni = 0; ni < 8; ni++) {
                    const int ng = n0 + ni * 8 + qc * 2;
                    float2 o;
                    o.x = acc[mi][ni][half*2+0] + bias[ng];
                    o.y = acc[mi][ni][half*2+1] + bias[ng + 1];
                    *(float2*)(dst + ng) = o;
                }
            }
        }
    }
}

// ---------------- tensor-core flash attention ----------------
// grid (SEQ/128, NB*NH), 256 threads (8 warps). Warp = 16 q-rows.
// K/V tiles 64x64 bf16 hi/lo in smem (128B swizzled rows).
// S = QK^T (3-term hi/lo), softmax in regs (FMA exp, no max), PV (3-term).
__global__ __launch_bounds__(256, 1) void attn_tc(const uint32_t* __restrict__ maskw)
{
    __shared__ char smb[32768];
    const uint32_t sb = smem_u32(smb);
    const int tid = threadIdx.x, w = tid >> 5, lane = tid & 31;
    const int bh = blockIdx.y, q0 = blockIdx.x * 128;
    const int r = lane >> 2, qc2 = (lane & 3) * 2;
    const float SC = 0.125f * 1.44269504f;   // scale * log2(e)

    // ---- stage Q tile (hi at 0, lo at 16K), then ldmatrix into regs ----
    {
        const __nv_bfloat16* Qh = g_Qh + ((size_t)bh * SEQ + q0) * HD;
        const __nv_bfloat16* Ql = g_Ql + ((size_t)bh * SEQ + q0) * HD;
        const int row = tid >> 1, cg = (tid & 1) * 4;
        #pragma unroll
        for (int c = 0; c < 4; c++) {
            const uint32_t off = sw128((uint32_t)(row * 128 + (cg + c) * 16));
            *(uint4*)(smb + off)         = ((const uint4*)(Qh + row * HD))[cg + c];
            *(uint4*)(smb + 16384 + off) = ((const uint4*)(Ql + row * HD))[cg + c];
        }
    }
    __syncthreads();
    uint32_t qh[4][4], ql[4][4];
    {
        const int row = w * 16 + ((lane >> 3) & 1) * 8 + (lane & 7);
        #pragma unroll
        for (int kc = 0; kc < 4; kc++) {
            const int chunk = kc * 2 + (lane >> 4);
            const uint32_t off = sw128((uint32_t)(row * 128 + chunk * 16));
            ldsm_x4(sb + off, qh[kc]);
            ldsm_x4(sb + 16384 + off, ql[kc]);
        }
    }
    __syncthreads();

    float ctx[8][4];
    #pragma unroll
    for (int j = 0; j < 8; j++)
        #pragma unroll
        for (int e = 0; e < 4; e++) ctx[j][e] = 0.f;
    float lsum0 = 0.f, lsum1 = 0.f;

    const __nv_bfloat16* Kh = g_Kh + (size_t)bh * SEQ * HD;
    const __nv_bfloat16* Kl = g_Kl + (size_t)bh * SEQ * HD;
    const __nv_bfloat16* Vh = g_Vh + (size_t)bh * SEQ * HD;
    const __nv_bfloat16* Vl = g_Vl + (size_t)bh * SEQ * HD;
    const uint32_t* mrow0 = maskw + ((size_t)bh * SEQ + (q0 + w * 16 + r)) * SEQ;
    const uint32_t* mrow1 = mrow0 + (size_t)8 * SEQ;

    for (int kt = 0; kt < SEQ / 64; kt++) {
        __syncthreads();
        {   // fill Kh(0) Kl(8K) Vh(16K) Vl(24K): 64 threads per array, 1 row each
            const int arr = tid >> 6, row = tid & 63;
            const __nv_bfloat16* src =
                (arr == 0 ? Kh : arr == 1 ? Kl : arr == 2 ? Vh : Vl)
                + ((size_t)(kt * 64 + row)) * HD;
            char* dstb = smb + arr * 8192;
            #pragma unroll
            for (int c = 0; c < 8; c++) {
                const uint32_t off = sw128((uint32_t)(row * 128 + c * 16));
                *(uint4*)(dstb + off) = ((const uint4*)src)[c];
            }
        }
        __syncthreads();

        // ---- S = Q K^T ----
        float sacc[8][4];
        #pragma unroll
        for (int j = 0; j < 8; j++) {
            #pragma unroll
            for (int e = 0; e < 4; e++) sacc[j][e] = 0.f;
            uint32_t kbh[8], kbl[8];
            #pragma unroll
            for (int half = 0; half < 2; half++) {
                const int row = j * 8 + (lane & 7);
                const int chunk = half * 4 + (lane >> 3);
                const uint32_t off = sw128((uint32_t)(row * 128 + chunk * 16));
                ldsm_x4(sb + off, kbh + half * 4);
                ldsm_x4(sb + 8192 + off, kbl + half * 4);
            }
            #pragma unroll
            for (int kc = 0; kc < 4; kc++) {
                const int i0 = (kc >> 1) * 4 + (kc & 1) * 2;
                mma16816(sacc[j], qh[kc], kbh[i0], kbh[i0 + 1]);
                mma16816(sacc[j], qh[kc], kbl[i0], kbl[i0 + 1]);
                mma16816(sacc[j], ql[kc], kbh[i0], kbh[i0 + 1]);
            }
        }

        // ---- mask + exp + pack P fragments ----
        uint32_t pfh[4][4], pfl[4][4];
        const int kb = kt * 64;
        #pragma unroll
        for (int j = 0; j < 8; j++) {
            uint2 m0 = *(const uint2*)(mrow0 + kb + j * 8 + qc2);
            uint2 m1 = *(const uint2*)(mrow1 + kb + j * 8 + qc2);
            float p0 = m0.x ? fexp2(sacc[j][0] * SC) : 0.f;
            float p1 = m0.y ? fexp2(sacc[j][1] * SC) : 0.f;
            float p2 = m1.x ? fexp2(sacc[j][2] * SC) : 0.f;
            float p3 = m1.y ? fexp2(sacc[j][3] * SC) : 0.f;
            lsum0 += p0 + p1;
            lsum1 += p2 + p3;
            uint32_t h01 = packbf(p0, p1);
            uint32_t h23 = packbf(p2, p3);
            float r0 = p0 - __bfloat162float(((__nv_bfloat162*)&h01)->x);
            float r1 = p1 - __bfloat162float(((__nv_bfloat162*)&h01)->y);
            float r2 = p2 - __bfloat162float(((__nv_bfloat162*)&h23)->x);
            float r3 = p3 - __bfloat162float(((__nv_bfloat162*)&h23)->y);
            pfh[j >> 1][(j & 1) * 2 + 0] = h01;
            pfh[j >> 1][(j & 1) * 2 + 1] = h23;
            pfl[j >> 1][(j & 1) * 2 + 0] = packbf(r0, r1);
            pfl[j >> 1][(j & 1) * 2 + 1] = packbf(r2, r3);
        }

        // ---- ctx += P V ----
        #pragma unroll
        for (int kc = 0; kc < 4; kc++) {
            #pragma unroll
            for (int dp = 0; dp < 4; dp++) {
                const int row = kc * 16 + ((lane >> 3) & 1) * 8 + (lane & 7);
                const int chunk = dp * 2 + (lane >> 4);
                const uint32_t off = sw128((uint32_t)(row * 128 + chunk * 16));
                uint32_t vb[4], vc[4];
                ldsm_x4t(sb + 16384 + off, vb);   // Vh
                ldsm_x4t(sb + 24576 + off, vc);   // Vl
                mma16816(ctx[dp*2],   pfh[kc], vb[0], vb[1]);
                mma16816(ctx[dp*2],   pfl[kc], vb[0], vb[1]);
                mma16816(ctx[dp*2],   pfh[kc], vc[0], vc[1]);
                mma16816(ctx[dp*2+1], pfh[kc], vb[2], vb[3]);
                mma16816(ctx[dp*2+1], pfl[kc], vb[2], vb[3]);
                mma16816(ctx[dp*2+1], pfh[kc], vc[2], vc[3]);
            }
        }
    }

    // ---- normalize + write ctx as bf16 hi/lo into [b, s, h*64+d] ----
    lsum0 += __shfl_xor_sync(0xffffffffu, lsum0, 1);
    lsum0 += __shfl_xor_sync(0xffffffffu, lsum0, 2);
    lsum1 += __shfl_xor_sync(0xffffffffu, lsum1, 1);
    lsum1 += __shfl_xor_sync(0xffffffffu, lsum1, 2);
    const float inv0 = (lsum0 > 0.f) ? 1.f / lsum0 : 0.f;
    const float inv1 = (lsum1 > 0.f) ? 1.f / lsum1 : 0.f;
    const int b = bh >> 4, h = bh & (NH - 1);
    const int s0 = q0 + w * 16 + r;
    const size_t base0 = ((size_t)b * SEQ + s0) * DM + h * 64;
    const size_t base1 = base0 + (size_t)8 * DM;
    #pragma unroll
    for (int j = 0; j < 8; j++) {
        const int d = j * 8 + qc2;
        float v0 = ctx[j][0] * inv0, v1 = ctx[j][1] * inv0;
        float v2 = ctx[j][2] * inv1, v3 = ctx[j][3] * inv1;
        __nv_bfloat16 h0 = __float2bfloat16(v0), h1 = __float2bfloat16(v1);
        __nv_bfloat16 h2 = __float2bfloat16(v2), h3 = __float2bfloat16(v3);
        __nv_bfloat162 hh0; hh0.x = h0; hh0.y = h1;
        __nv_bfloat162 hh1; hh1.x = h2; hh1.y = h3;
        __nv_bfloat162 ll0, ll1;
        ll0.x = __float2bfloat16(v0 - __bfloat162float(h0));
        ll0.y = __float2bfloat16(v1 - __bfloat162float(h1));
        ll1.x = __float2bfloat16(v2 - __bfloat162float(h2));
        ll1.y = __float2bfloat16(v3 - __bfloat162float(h3));
        *(__nv_bfloat162*)(g_ch + base0 + d) = hh0;
        *(__nv_bfloat162*)(g_cl + base0 + d) = ll0;
        *(__nv_bfloat162*)(g_ch + base1 + d) = hh1;
        *(__nv_bfloat162*)(g_cl + base1 + d) = ll1;
    }
}

// ---------------- launch ----------------
extern "C" void kernel_launch(void* const* d_in, const int* in_sizes, int n_in,
                              void* d_out, int out_size)
{
    const float* x  = (const float*)d_in[0];
    const uint32_t* maskw = (const uint32_t*)d_in[1];
    const float* Wq = (const float*)d_in[2];
    const float* bq = (const float*)d_in[3];
    const float* Wk = (const float*)d_in[4];
    const float* bk = (const float*)d_in[5];
    const float* Wv = (const float*)d_in[6];
    const float* bv = (const float*)d_in[7];
    const float* Wo = (const float*)d_in[8];
    const float* bo = (const float*)d_in[9];
    float* out = (float*)d_out;

    __nv_bfloat16 *xh, *xl, *ch, *cl, *wqh, *wql, *wkh, *wkl, *wvh, *wvl, *woh, *wol;
    __nv_bfloat16 *qh, *qlp, *kh, *kl, *vh, *vl;
    cudaGetSymbolAddress((void**)&xh,  g_xh);  cudaGetSymbolAddress((void**)&xl,  g_xl);
    cudaGetSymbolAddress((void**)&ch,  g_ch);  cudaGetSymbolAddress((void**)&cl,  g_cl);
    cudaGetSymbolAddress((void**)&wqh, g_wqh); cudaGetSymbolAddress((void**)&wql, g_wql);
    cudaGetSymbolAddress((void**)&wkh, g_wkh); cudaGetSymbolAddress((void**)&wkl, g_wkl);
    cudaGetSymbolAddress((void**)&wvh, g_wvh); cudaGetSymbolAddress((void**)&wvl, g_wvl);
    cudaGetSymbolAddress((void**)&woh, g_woh); cudaGetSymbolAddress((void**)&wol, g_wol);
    cudaGetSymbolAddress((void**)&qh,  g_Qh);  cudaGetSymbolAddress((void**)&qlp, g_Ql);
    cudaGetSymbolAddress((void**)&kh,  g_Kh);  cudaGetSymbolAddress((void**)&kl,  g_Kl);
    cudaGetSymbolAddress((void**)&vh,  g_Vh);  cudaGetSymbolAddress((void**)&vl,  g_Vl);

    const int nx4 = (int)((size_t)MTOT * DM / 4);
    const int nw4 = (int)((size_t)DM * DM / 4);
    conv_hilo<<<nx4/256, 256>>>((const float4*)x,  (__nv_bfloat162*)xh,  (__nv_bfloat162*)xl,  nx4);
    conv_hilo<<<nw4/256, 256>>>((const float4*)Wq, (__nv_bfloat162*)wqh, (__nv_bfloat162*)wql, nw4);
    conv_hilo<<<nw4/256, 256>>>((const float4*)Wk, (__nv_bfloat162*)wkh, (__nv_bfloat162*)wkl, nw4);
    conv_hilo<<<nw4/256, 256>>>((const float4*)Wv, (__nv_bfloat162*)wvh, (__nv_bfloat162*)wvl, nw4);
    conv_hilo<<<nw4/256, 256>>>((const float4*)Wo, (__nv_bfloat162*)woh, (__nv_bfloat162*)wol, nw4);

    dim3 ggrid(DM / 128, MTOT / 128);   // (8, 32)
    gemm_tc<0><<<ggrid, 256>>>(xh, xl, wqh, wql, bq, qh, qlp, nullptr);
    gemm_tc<1><<<ggrid, 256>>>(xh, xl, wkh, wkl, bk, kh, kl, nullptr);
    gemm_tc<2><<<ggrid, 256>>>(xh, xl, wvh, wvl, bv, vh, vl, nullptr);

    dim3 agrid(SEQ / 128, NB * NH);     // (16, 32)
    attn_tc<<<agrid, 256>>>(maskw);

    gemm_tc<3><<<ggrid, 256>>>(ch, cl, woh, wol, bo, nullptr, nullptr, out);
}

// round 6
// speedup vs baseline: 3.4646x; 1.3881x over previous
#include <cuda_runtime.h>
#include <cuda_fp16.h>
#include <math.h>
#include <stdint.h>

#define NH   16
#define HD   64
#define NB   2
#define SEQ  2048
#define DM   1024
#define MTOT (NB*SEQ)

// ---------------- device scratch (allocation-free rule) ----------------
__device__ __align__(256) __half g_Qh[(size_t)NB*NH*SEQ*HD];
__device__ __align__(256) __half g_Kh[(size_t)NB*NH*SEQ*HD], g_Kl[(size_t)NB*NH*SEQ*HD];
__device__ __align__(256) __half g_Vh[(size_t)NB*NH*SEQ*HD], g_Vl[(size_t)NB*NH*SEQ*HD];
__device__ __align__(256) __half g_xh[(size_t)MTOT*DM];
__device__ __align__(256) __half g_ch[(size_t)MTOT*DM];
__device__ __align__(256) __half g_wqh[(size_t)DM*DM], g_wql[(size_t)DM*DM];
__device__ __align__(256) __half g_wkh[(size_t)DM*DM], g_wkl[(size_t)DM*DM];
__device__ __align__(256) __half g_wvh[(size_t)DM*DM], g_wvl[(size_t)DM*DM];
__device__ __align__(256) __half g_woh[(size_t)DM*DM], g_wol[(size_t)DM*DM];

// ---------------- helpers ----------------
__device__ __forceinline__ uint32_t smem_u32(const void* p) {
    uint32_t a;
    asm("{ .reg .u64 t; cvta.to.shared.u64 t, %1; cvt.u32.u64 %0, t; }" : "=r"(a) : "l"(p));
    return a;
}
__device__ __forceinline__ uint32_t sw128(uint32_t o) {   // 128B rows
    return o ^ (((o >> 7) & 7u) << 4);
}
__device__ __forceinline__ uint32_t sw64(uint32_t o) {    // 64B rows
    return o ^ (((o >> 7) & 3u) << 4);
}
__device__ __forceinline__ void cpasync16(uint32_t dst, const void* src) {
    asm volatile("cp.async.cg.shared.global [%0], [%1], 16;" :: "r"(dst), "l"(src));
}
__device__ __forceinline__ void cp_commit() {
    asm volatile("cp.async.commit_group;" ::: "memory");
}
__device__ __forceinline__ void cp_wait1() {
    asm volatile("cp.async.wait_group 1;" ::: "memory");
}
__device__ __forceinline__ void cp_wait0() {
    asm volatile("cp.async.wait_group 0;" ::: "memory");
}
__device__ __forceinline__ void ldsm_x4(uint32_t a, uint32_t* r) {
    asm volatile("ldmatrix.sync.aligned.m8n8.x4.shared.b16 {%0,%1,%2,%3}, [%4];"
                 : "=r"(r[0]), "=r"(r[1]), "=r"(r[2]), "=r"(r[3]) : "r"(a));
}
__device__ __forceinline__ void ldsm_x4t(uint32_t a, uint32_t* r) {
    asm volatile("ldmatrix.sync.aligned.m8n8.x4.trans.shared.b16 {%0,%1,%2,%3}, [%4];"
                 : "=r"(r[0]), "=r"(r[1]), "=r"(r[2]), "=r"(r[3]) : "r"(a));
}
__device__ __forceinline__ void mma16816(float* c, const uint32_t* a,
                                         uint32_t b0, uint32_t b1) {
    asm volatile(
        "mma.sync.aligned.m16n8k16.row.col.f32.f16.f16.f32 "
        "{%0,%1,%2,%3}, {%4,%5,%6,%7}, {%8,%9}, {%0,%1,%2,%3};"
        : "+f"(c[0]), "+f"(c[1]), "+f"(c[2]), "+f"(c[3])
        : "r"(a[0]), "r"(a[1]), "r"(a[2]), "r"(a[3]), "r"(b0), "r"(b1));
}
// FMA-only 2^e (no MUFU), e pre-multiplied by log2
__device__ __forceinline__ float fexp2(float e) {
    float t = e + 12582912.0f;
    int   ib = __float_as_int(t);
    float r = t - 12582912.0f;
    float f = e - r;
    float p = 1.3333558e-3f;
    p = fmaf(p, f, 9.6181291e-3f);
    p = fmaf(p, f, 5.5504109e-2f);
    p = fmaf(p, f, 2.4022651e-1f);
    p = fmaf(p, f, 6.9314718e-1f);
    p = fmaf(p, f, 1.0f);
    return __int_as_float((ib + (127 - 0x4B400000)) << 23) * p;
}
__device__ __forceinline__ uint32_t packh(float lo, float hi) {
    __half2 h = __floats2half2_rn(lo, hi);
    return *(uint32_t*)&h;
}

// ---------------- conversions ----------------
__global__ __launch_bounds__(256) void conv_s(const float4* __restrict__ src,
                                              __half2* __restrict__ dst, int n4) {
    int i = blockIdx.x * 256 + threadIdx.x;
    if (i >= n4) return;
    float4 v = src[i];
    dst[2*i]   = __floats2half2_rn(v.x, v.y);
    dst[2*i+1] = __floats2half2_rn(v.z, v.w);
}
__global__ __launch_bounds__(256) void conv_p(const float4* __restrict__ src,
                                              __half2* __restrict__ hi,
                                              __half2* __restrict__ lo, int n4) {
    int i = blockIdx.x * 256 + threadIdx.x;
    if (i >= n4) return;
    float4 v = src[i];
    __half hx = __float2half_rn(v.x), hy = __float2half_rn(v.y);
    __half hz = __float2half_rn(v.z), hw = __float2half_rn(v.w);
    hi[2*i]   = __halves2half2(hx, hy);
    hi[2*i+1] = __halves2half2(hz, hw);
    lo[2*i]   = __floats2half2_rn(v.x - __half2float(hx), v.y - __half2float(hy));
    lo[2*i+1] = __floats2half2_rn(v.z - __half2float(hz), v.w - __half2float(hw));
}

// ---------------- fp16 GEMM: Out[M,N] = A[M,K]@(Bh+Bl)[N,K]^T + bias ------
// A single fp16, B hi/lo pair -> 2 MMAs per output. CTA 128x128, 8 warps,
// BK=32, cp.async 2-stage pipeline. DST 0: half single out [b,h,s,d];
// DST 1/2: half pair out [b,h,s,d]; DST 3: fp32 row-major.
#define GSTG 24576   // stage stride: A 8K + Bh 8K + Bl 8K
template<int DST>
__global__ __launch_bounds__(256, 2)
void gemm_tc(const __half* __restrict__ A_, const __half* __restrict__ Bh_,
             const __half* __restrict__ Bl_, const float* __restrict__ bias,
             __half* __restrict__ OutH, __half* __restrict__ OutL,
             float* __restrict__ Out)
{
    extern __shared__ char smb[];
    const uint32_t sb = smem_u32(smb);
    const int tid = threadIdx.x;
    const int wid = tid >> 5;
    const int lid = tid & 31;
    const int wm = wid & 3;
    const int wn = wid >> 2;
    const int bm = blockIdx.y * 128;
    const int bn = blockIdx.x * 128;

    float acc[2][8][4];
    #pragma unroll
    for (int mi = 0; mi < 2; mi++)
        #pragma unroll
        for (int ni = 0; ni < 8; ni++)
            #pragma unroll
            for (int e = 0; e < 4; e++) acc[mi][ni][e] = 0.f;

    // stage loader: 512 x 16B per array, 2 per thread per array
    auto load_stage = [&](int c, int buf) {
        const uint32_t base = sb + buf * GSTG;
        #pragma unroll
        for (int p = 0; p < 2; p++) {
            const int id = tid + p * 256;
            const int row = id >> 2, ch = id & 3;
            const uint32_t so = sw64((uint32_t)(row * 64 + ch * 16));
            const size_t ga = (size_t)(bm + row) * (DM / 8) + c * 4 + ch;
            const size_t gb = (size_t)(bn + row) * (DM / 8) + c * 4 + ch;
            cpasync16(base + so,         (const uint4*)A_  + ga);
            cpasync16(base + 8192 + so,  (const uint4*)Bh_ + gb);
            cpasync16(base + 16384 + so, (const uint4*)Bl_ + gb);
        }
        cp_commit();
    };

    load_stage(0, 0);

    for (int c = 0; c < DM / 32; c++) {
        if (c < DM / 32 - 1) { load_stage(c + 1, (c + 1) & 1); cp_wait1(); }
        else cp_wait0();
        __syncthreads();

        const uint32_t base = sb + (c & 1) * GSTG;
        #pragma unroll
        for (int ks = 0; ks < 2; ks++) {
            uint32_t ah[2][4];
            #pragma unroll
            for (int mi = 0; mi < 2; mi++) {
                const int row = wm * 32 + mi * 16 + (lid & 15);
                const int colb = (ks * 16 + (lid >> 4) * 8) * 2;
                ldsm_x4(base + sw64((uint32_t)(row * 64 + colb)), ah[mi]);
            }
            uint32_t bh[8][2], bl[8][2];
            #pragma unroll
            for (int nj = 0; nj < 4; nj++) {
                const int row = wn * 64 + nj * 16 + ((lid >> 4) << 3) + (lid & 7);
                const int colb = (ks * 16 + ((lid >> 3) & 1) * 8) * 2;
                const uint32_t off = sw64((uint32_t)(row * 64 + colb));
                uint32_t t[4];
                ldsm_x4(base + 8192 + off, t);
                bh[nj*2][0] = t[0]; bh[nj*2][1] = t[1];
                bh[nj*2+1][0] = t[2]; bh[nj*2+1][1] = t[3];
                ldsm_x4(base + 16384 + off, t);
                bl[nj*2][0] = t[0]; bl[nj*2][1] = t[1];
                bl[nj*2+1][0] = t[2]; bl[nj*2+1][1] = t[3];
            }
            #pragma unroll
            for (int mi = 0; mi < 2; mi++)
                #pragma unroll
                for (int ni = 0; ni < 8; ni++) {
                    mma16816(acc[mi][ni], ah[mi], bh[ni][0], bh[ni][1]);
                    mma16816(acc[mi][ni], ah[mi], bl[ni][0], bl[ni][1]);
                }
        }
        __syncthreads();
    }

    const int qr = lid >> 2, qc = lid & 3;
    #pragma unroll
    for (int mi = 0; mi < 2; mi++) {
        #pragma unroll
        for (int half = 0; half < 2; half++) {
            const int m = bm + wm * 32 + mi * 16 + half * 8 + qr;
            const int n0 = bn + wn * 64;
            if (DST <= 2) {
                const int b = m >> 11, s = m & (SEQ - 1);
                const int h = n0 >> 6;
                const size_t base = ((size_t)(b * NH + h) * SEQ + s) * HD;
                #pragma unroll
                for (int ni = 0; ni < 8; ni++) {
                    const int nloc = ni * 8 + qc * 2;
                    const int ng = n0 + nloc;
                    float v0 = acc[mi][ni][half*2+0] + bias[ng];
                    float v1 = acc[mi][ni][half*2+1] + bias[ng + 1];
                    __half h0 = __float2half_rn(v0);
                    __half h1 = __float2half_rn(v1);
                    *(__half2*)(OutH + base + nloc) = __halves2half2(h0, h1);
                    if (DST >= 1) {
                        *(__half2*)(OutL + base + nloc) = __floats2half2_rn(
                            v0 - __half2float(h0), v1 - __half2float(h1));
                    }
                }
            } else {
                float* dst = Out + (size_t)m * DM;
                #pragma unroll
                for (int ni = 0; ni < 8; ni++) {
                    const int ng = n0 + ni * 8 + qc * 2;
                    float2 o;
                    o.x = acc[mi][ni][half*2+0] + bias[ng];
                    o.y = acc[mi][ni][half*2+1] + bias[ng + 1];
                    *(float2*)(dst + ng) = o;
                }
            }
        }
    }
}

// ---------------- fp16 tensor-core flash attention ----------------
// grid (SEQ/128, NB*NH), 256 threads. Q single fp16 (regs), K/V hi/lo pairs
// in cp.async double-buffered smem tiles (64x64). S = Q(Kh+Kl)^T (2 MMAs),
// P single fp16, ctx += P(Vh+Vl) (2 MMAs). FMA softmax, no running max.
#define ASTG 32768   // stage stride: Kh 8K + Kl 8K + Vh 8K + Vl 8K
__global__ __launch_bounds__(256, 1) void attn_tc(const uint32_t* __restrict__ maskw)
{
    extern __shared__ char smb[];
    const uint32_t sb = smem_u32(smb);
    const int tid = threadIdx.x, w = tid >> 5, lane = tid & 31;
    const int bh = blockIdx.y, q0 = blockIdx.x * 128;
    const int r = lane >> 2, qc2 = (lane & 3) * 2;
    const float SC = 0.125f * 1.44269504f;

    // ---- stage Q tile into stage-0 area, pull fragments to regs ----
    {
        const __half* Q = g_Qh + ((size_t)bh * SEQ + q0) * HD;
        const int row = tid >> 1, cg = (tid & 1) * 4;
        #pragma unroll
        for (int c = 0; c < 4; c++) {
            const uint32_t off = sw128((uint32_t)(row * 128 + (cg + c) * 16));
            *(uint4*)(smb + off) = ((const uint4*)(Q + row * HD))[cg + c];
        }
    }
    __syncthreads();
    uint32_t qh[4][4];
    {
        const int row = w * 16 + ((lane >> 3) & 1) * 8 + (lane & 7);
        #pragma unroll
        for (int kc = 0; kc < 4; kc++) {
            const int chunk = kc * 2 + (lane >> 4);
            ldsm_x4(sb + sw128((uint32_t)(row * 128 + chunk * 16)), qh[kc]);
        }
    }
    __syncthreads();

    float ctx[8][4];
    #pragma unroll
    for (int j = 0; j < 8; j++)
        #pragma unroll
        for (int e = 0; e < 4; e++) ctx[j][e] = 0.f;
    float lsum0 = 0.f, lsum1 = 0.f;

    const __half* Kh = g_Kh + (size_t)bh * SEQ * HD;
    const __half* Kl = g_Kl + (size_t)bh * SEQ * HD;
    const __half* Vh = g_Vh + (size_t)bh * SEQ * HD;
    const __half* Vl = g_Vl + (size_t)bh * SEQ * HD;
    const uint32_t* mrow0 = maskw + ((size_t)bh * SEQ + (q0 + w * 16 + r)) * SEQ;
    const uint32_t* mrow1 = mrow0 + (size_t)8 * SEQ;

    // tile loader: 4 arrays x 64 rows x 8 chunks; thread -> (array, row), 8 chunks
    auto load_tile = [&](int kt, int buf) {
        const int arr = tid >> 6, row = tid & 63;
        const __half* src =
            (arr == 0 ? Kh : arr == 1 ? Kl : arr == 2 ? Vh : Vl)
            + ((size_t)(kt * 64 + row)) * HD;
        const uint32_t dstb = sb + buf * ASTG + arr * 8192;
        #pragma unroll
        for (int c = 0; c < 8; c++) {
            cpasync16(dstb + sw128((uint32_t)(row * 128 + c * 16)),
                      (const uint4*)src + c);
        }
        cp_commit();
    };

    load_tile(0, 0);

    for (int kt = 0; kt < SEQ / 64; kt++) {
        if (kt < SEQ / 64 - 1) { load_tile(kt + 1, (kt + 1) & 1); cp_wait1(); }
        else cp_wait0();
        __syncthreads();
        const uint32_t base = sb + (kt & 1) * ASTG;

        // ---- S = Q (Kh + Kl)^T ----
        float sacc[8][4];
        #pragma unroll
        for (int j = 0; j < 8; j++) {
            #pragma unroll
            for (int e = 0; e < 4; e++) sacc[j][e] = 0.f;
            uint32_t kbh[8], kbl[8];
            #pragma unroll
            for (int half = 0; half < 2; half++) {
                const int row = j * 8 + (lane & 7);
                const int chunk = half * 4 + (lane >> 3);
                const uint32_t off = sw128((uint32_t)(row * 128 + chunk * 16));
                ldsm_x4(base + off, kbh + half * 4);
                ldsm_x4(base + 8192 + off, kbl + half * 4);
            }
            #pragma unroll
            for (int kc = 0; kc < 4; kc++) {
                const int i0 = (kc >> 1) * 4 + (kc & 1) * 2;
                mma16816(sacc[j], qh[kc], kbh[i0], kbh[i0 + 1]);
                mma16816(sacc[j], qh[kc], kbl[i0], kbl[i0 + 1]);
            }
        }

        // ---- mask + exp + pack P (single fp16) ----
        uint32_t pf[4][4];
        const int kb = kt * 64;
        #pragma unroll
        for (int j = 0; j < 8; j++) {
            uint2 m0 = *(const uint2*)(mrow0 + kb + j * 8 + qc2);
            uint2 m1 = *(const uint2*)(mrow1 + kb + j * 8 + qc2);
            float p0 = m0.x ? fexp2(sacc[j][0] * SC) : 0.f;
            float p1 = m0.y ? fexp2(sacc[j][1] * SC) : 0.f;
            float p2 = m1.x ? fexp2(sacc[j][2] * SC) : 0.f;
            float p3 = m1.y ? fexp2(sacc[j][3] * SC) : 0.f;
            lsum0 += p0 + p1;
            lsum1 += p2 + p3;
            pf[j >> 1][(j & 1) * 2 + 0] = packh(p0, p1);
            pf[j >> 1][(j & 1) * 2 + 1] = packh(p2, p3);
        }

        // ---- ctx += P (Vh + Vl) ----
        #pragma unroll
        for (int kc = 0; kc < 4; kc++) {
            #pragma unroll
            for (int dp = 0; dp < 4; dp++) {
                const int row = kc * 16 + ((lane >> 3) & 1) * 8 + (lane & 7);
                const int chunk = dp * 2 + (lane >> 4);
                const uint32_t off = sw128((uint32_t)(row * 128 + chunk * 16));
                uint32_t vb[4], vc[4];
                ldsm_x4t(base + 16384 + off, vb);
                ldsm_x4t(base + 24576 + off, vc);
                mma16816(ctx[dp*2],   pf[kc], vb[0], vb[1]);
                mma16816(ctx[dp*2],   pf[kc], vc[0], vc[1]);
                mma16816(ctx[dp*2+1], pf[kc], vb[2], vb[3]);
                mma16816(ctx[dp*2+1], pf[kc], vc[2], vc[3]);
            }
        }
        __syncthreads();
    }

    // ---- normalize + write ctx (single fp16) into [b, s, h*64+d] ----
    lsum0 += __shfl_xor_sync(0xffffffffu, lsum0, 1);
    lsum0 += __shfl_xor_sync(0xffffffffu, lsum0, 2);
    lsum1 += __shfl_xor_sync(0xffffffffu, lsum1, 1);
    lsum1 += __shfl_xor_sync(0xffffffffu, lsum1, 2);
    const float inv0 = (lsum0 > 0.f) ? 1.f / lsum0 : 0.f;
    const float inv1 = (lsum1 > 0.f) ? 1.f / lsum1 : 0.f;
    const int b = bh >> 4, h = bh & (NH - 1);
    const int s0 = q0 + w * 16 + r;
    const size_t base0 = ((size_t)b * SEQ + s0) * DM + h * 64;
    const size_t base1 = base0 + (size_t)8 * DM;
    #pragma unroll
    for (int j = 0; j < 8; j++) {
        const int d = j * 8 + qc2;
        *(__half2*)(g_ch + base0 + d) =
            __floats2half2_rn(ctx[j][0] * inv0, ctx[j][1] * inv0);
        *(__half2*)(g_ch + base1 + d) =
            __floats2half2_rn(ctx[j][2] * inv1, ctx[j][3] * inv1);
    }
}

// ---------------- launch ----------------
extern "C" void kernel_launch(void* const* d_in, const int* in_sizes, int n_in,
                              void* d_out, int out_size)
{
    const float* x  = (const float*)d_in[0];
    const uint32_t* maskw = (const uint32_t*)d_in[1];
    const float* Wq = (const float*)d_in[2];
    const float* bq = (const float*)d_in[3];
    const float* Wk = (const float*)d_in[4];
    const float* bk = (const float*)d_in[5];
    const float* Wv = (const float*)d_in[6];
    const float* bv = (const float*)d_in[7];
    const float* Wo = (const float*)d_in[8];
    const float* bo = (const float*)d_in[9];
    float* out = (float*)d_out;

    __half *xh, *ch, *wqh, *wql, *wkh, *wkl, *wvh, *wvl, *woh, *wol;
    __half *qh, *kh, *kl, *vh, *vl;
    cudaGetSymbolAddress((void**)&xh,  g_xh);
    cudaGetSymbolAddress((void**)&ch,  g_ch);
    cudaGetSymbolAddress((void**)&wqh, g_wqh); cudaGetSymbolAddress((void**)&wql, g_wql);
    cudaGetSymbolAddress((void**)&wkh, g_wkh); cudaGetSymbolAddress((void**)&wkl, g_wkl);
    cudaGetSymbolAddress((void**)&wvh, g_wvh); cudaGetSymbolAddress((void**)&wvl, g_wvl);
    cudaGetSymbolAddress((void**)&woh, g_woh); cudaGetSymbolAddress((void**)&wol, g_wol);
    cudaGetSymbolAddress((void**)&qh,  g_Qh);
    cudaGetSymbolAddress((void**)&kh,  g_Kh);  cudaGetSymbolAddress((void**)&kl,  g_Kl);
    cudaGetSymbolAddress((void**)&vh,  g_Vh);  cudaGetSymbolAddress((void**)&vl,  g_Vl);

    const int GEMM_SMEM = 2 * GSTG;   // 49152
    const int ATTN_SMEM = 2 * ASTG;   // 65536
    cudaFuncSetAttribute(gemm_tc<0>, cudaFuncAttributeMaxDynamicSharedMemorySize, GEMM_SMEM);
    cudaFuncSetAttribute(gemm_tc<1>, cudaFuncAttributeMaxDynamicSharedMemorySize, GEMM_SMEM);
    cudaFuncSetAttribute(gemm_tc<2>, cudaFuncAttributeMaxDynamicSharedMemorySize, GEMM_SMEM);
    cudaFuncSetAttribute(gemm_tc<3>, cudaFuncAttributeMaxDynamicSharedMemorySize, GEMM_SMEM);
    cudaFuncSetAttribute(attn_tc,    cudaFuncAttributeMaxDynamicSharedMemorySize, ATTN_SMEM);

    const int nx4 = (int)((size_t)MTOT * DM / 4);
    const int nw4 = (int)((size_t)DM * DM / 4);
    conv_s<<<nx4/256, 256>>>((const float4*)x,  (__half2*)xh,  nx4);
    conv_p<<<nw4/256, 256>>>((const float4*)Wq, (__half2*)wqh, (__half2*)wql, nw4);
    conv_p<<<nw4/256, 256>>>((const float4*)Wk, (__half2*)wkh, (__half2*)wkl, nw4);
    conv_p<<<nw4/256, 256>>>((const float4*)Wv, (__half2*)wvh, (__half2*)wvl, nw4);
    conv_p<<<nw4/256, 256>>>((const float4*)Wo, (__half2*)woh, (__half2*)wol, nw4);

    dim3 ggrid(DM / 128, MTOT / 128);   // (8, 32)
    gemm_tc<0><<<ggrid, 256, GEMM_SMEM>>>(xh, wqh, wql, bq, qh, nullptr, nullptr);
    gemm_tc<1><<<ggrid, 256, GEMM_SMEM>>>(xh, wkh, wkl, bk, kh, kl, nullptr);
    gemm_tc<2><<<ggrid, 256, GEMM_SMEM>>>(xh, wvh, wvl, bv, vh, vl, nullptr);

    dim3 agrid(SEQ / 128, NB * NH);     // (16, 32)
    attn_tc<<<agrid, 256, ATTN_SMEM>>>(maskw);

    gemm_tc<3><<<ggrid, 256, GEMM_SMEM>>>(ch, woh, wol, bo, nullptr, nullptr, out);
}

// round 7
// speedup vs baseline: 5.3243x; 1.5368x over previous
#include <cuda_runtime.h>
#include <cuda_fp16.h>
#include <math.h>
#include <stdint.h>

#define NH   16
#define HD   64
#define NB   2
#define SEQ  2048
#define DM   1024
#define MTOT (NB*SEQ)

// ---------------- device scratch (allocation-free rule) ----------------
__device__ __align__(256) __half g_Qh[(size_t)NB*NH*SEQ*HD];
__device__ __align__(256) __half g_Kh[(size_t)NB*NH*SEQ*HD];
__device__ __align__(256) __half g_Vh[(size_t)NB*NH*SEQ*HD];
__device__ __align__(256) __half g_xh[(size_t)MTOT*DM];
__device__ __align__(256) __half g_ch[(size_t)MTOT*DM];
__device__ __align__(256) __half g_wqh[(size_t)DM*DM];
__device__ __align__(256) __half g_wkh[(size_t)DM*DM];
__device__ __align__(256) __half g_wvh[(size_t)DM*DM];
__device__ __align__(256) __half g_woh[(size_t)DM*DM];

// ---------------- helpers ----------------
__device__ __forceinline__ uint32_t smem_u32(const void* p) {
    uint32_t a;
    asm("{ .reg .u64 t; cvta.to.shared.u64 t, %1; cvt.u32.u64 %0, t; }" : "=r"(a) : "l"(p));
    return a;
}
__device__ __forceinline__ uint32_t sw128(uint32_t o) {   // 128B rows
    return o ^ (((o >> 7) & 7u) << 4);
}
__device__ __forceinline__ uint32_t sw64(uint32_t o) {    // 64B rows
    return o ^ (((o >> 7) & 3u) << 4);
}
__device__ __forceinline__ void cpasync16(uint32_t dst, const void* src) {
    asm volatile("cp.async.cg.shared.global [%0], [%1], 16;" :: "r"(dst), "l"(src));
}
__device__ __forceinline__ void cp_commit() {
    asm volatile("cp.async.commit_group;" ::: "memory");
}
__device__ __forceinline__ void cp_wait1() {
    asm volatile("cp.async.wait_group 1;" ::: "memory");
}
__device__ __forceinline__ void cp_wait0() {
    asm volatile("cp.async.wait_group 0;" ::: "memory");
}
__device__ __forceinline__ void ldsm_x4(uint32_t a, uint32_t* r) {
    asm volatile("ldmatrix.sync.aligned.m8n8.x4.shared.b16 {%0,%1,%2,%3}, [%4];"
                 : "=r"(r[0]), "=r"(r[1]), "=r"(r[2]), "=r"(r[3]) : "r"(a));
}
__device__ __forceinline__ void ldsm_x4t(uint32_t a, uint32_t* r) {
    asm volatile("ldmatrix.sync.aligned.m8n8.x4.trans.shared.b16 {%0,%1,%2,%3}, [%4];"
                 : "=r"(r[0]), "=r"(r[1]), "=r"(r[2]), "=r"(r[3]) : "r"(a));
}
__device__ __forceinline__ void mma16816(float* c, const uint32_t* a,
                                         uint32_t b0, uint32_t b1) {
    asm volatile(
        "mma.sync.aligned.m16n8k16.row.col.f32.f16.f16.f32 "
        "{%0,%1,%2,%3}, {%4,%5,%6,%7}, {%8,%9}, {%0,%1,%2,%3};"
        : "+f"(c[0]), "+f"(c[1]), "+f"(c[2]), "+f"(c[3])
        : "r"(a[0]), "r"(a[1]), "r"(a[2]), "r"(a[3]), "r"(b0), "r"(b1));
}
// FMA-only 2^e (no MUFU), e pre-multiplied by log2
__device__ __forceinline__ float fexp2(float e) {
    float t = e + 12582912.0f;
    int   ib = __float_as_int(t);
    float r = t - 12582912.0f;
    float f = e - r;
    float p = 1.3333558e-3f;
    p = fmaf(p, f, 9.6181291e-3f);
    p = fmaf(p, f, 5.5504109e-2f);
    p = fmaf(p, f, 2.4022651e-1f);
    p = fmaf(p, f, 6.9314718e-1f);
    p = fmaf(p, f, 1.0f);
    return __int_as_float((ib + (127 - 0x4B400000)) << 23) * p;
}
__device__ __forceinline__ uint32_t packh(float lo, float hi) {
    __half2 h = __floats2half2_rn(lo, hi);
    return *(uint32_t*)&h;
}

// ---------------- conversion fp32 -> fp16 ----------------
__global__ __launch_bounds__(256) void conv_s(const float4* __restrict__ src,
                                              __half2* __restrict__ dst, int n4) {
    int i = blockIdx.x * 256 + threadIdx.x;
    if (i >= n4) return;
    float4 v = src[i];
    dst[2*i]   = __floats2half2_rn(v.x, v.y);
    dst[2*i+1] = __floats2half2_rn(v.z, v.w);
}

// ---------------- fp16 GEMM: Out[M,N] = A[M,K]@B[N,K]^T + bias ------------
// Single fp16 operands -> 1 MMA per output. CTA 128x128, 8 warps, BK=32,
// cp.async 2-stage pipeline. DST<=2: half out [b,h,s,d]; DST 3: fp32 rows.
#define GSTG 16384   // stage stride: A 8K + B 8K
template<int DST>
__global__ __launch_bounds__(256, 2)
void gemm_tc(const __half* __restrict__ A_, const __half* __restrict__ B_,
             const float* __restrict__ bias,
             __half* __restrict__ OutH, float* __restrict__ Out)
{
    extern __shared__ char smb[];
    const uint32_t sb = smem_u32(smb);
    const int tid = threadIdx.x;
    const int wid = tid >> 5;
    const int lid = tid & 31;
    const int wm = wid & 3;
    const int wn = wid >> 2;
    const int bm = blockIdx.y * 128;
    const int bn = blockIdx.x * 128;

    float acc[2][8][4];
    #pragma unroll
    for (int mi = 0; mi < 2; mi++)
        #pragma unroll
        for (int ni = 0; ni < 8; ni++)
            #pragma unroll
            for (int e = 0; e < 4; e++) acc[mi][ni][e] = 0.f;

    auto load_stage = [&](int c, int buf) {
        const uint32_t base = sb + buf * GSTG;
        #pragma unroll
        for (int p = 0; p < 2; p++) {
            const int id = tid + p * 256;
            const int row = id >> 2, ch = id & 3;
            const uint32_t so = sw64((uint32_t)(row * 64 + ch * 16));
            const size_t ga = (size_t)(bm + row) * (DM / 8) + c * 4 + ch;
            const size_t gb = (size_t)(bn + row) * (DM / 8) + c * 4 + ch;
            cpasync16(base + so,        (const uint4*)A_ + ga);
            cpasync16(base + 8192 + so, (const uint4*)B_ + gb);
        }
        cp_commit();
    };

    load_stage(0, 0);

    for (int c = 0; c < DM / 32; c++) {
        if (c < DM / 32 - 1) { load_stage(c + 1, (c + 1) & 1); cp_wait1(); }
        else cp_wait0();
        __syncthreads();

        const uint32_t base = sb + (c & 1) * GSTG;
        #pragma unroll
        for (int ks = 0; ks < 2; ks++) {
            uint32_t ah[2][4];
            #pragma unroll
            for (int mi = 0; mi < 2; mi++) {
                const int row = wm * 32 + mi * 16 + (lid & 15);
                const int colb = (ks * 16 + (lid >> 4) * 8) * 2;
                ldsm_x4(base + sw64((uint32_t)(row * 64 + colb)), ah[mi]);
            }
            uint32_t bh[8][2];
            #pragma unroll
            for (int nj = 0; nj < 4; nj++) {
                const int row = wn * 64 + nj * 16 + ((lid >> 4) << 3) + (lid & 7);
                const int colb = (ks * 16 + ((lid >> 3) & 1) * 8) * 2;
                uint32_t t[4];
                ldsm_x4(base + 8192 + sw64((uint32_t)(row * 64 + colb)), t);
                bh[nj*2][0] = t[0]; bh[nj*2][1] = t[1];
                bh[nj*2+1][0] = t[2]; bh[nj*2+1][1] = t[3];
            }
            #pragma unroll
            for (int mi = 0; mi < 2; mi++)
                #pragma unroll
                for (int ni = 0; ni < 8; ni++)
                    mma16816(acc[mi][ni], ah[mi], bh[ni][0], bh[ni][1]);
        }
        __syncthreads();
    }

    const int qr = lid >> 2, qc = lid & 3;
    #pragma unroll
    for (int mi = 0; mi < 2; mi++) {
        #pragma unroll
        for (int half = 0; half < 2; half++) {
            const int m = bm + wm * 32 + mi * 16 + half * 8 + qr;
            const int n0 = bn + wn * 64;
            if (DST <= 2) {
                const int b = m >> 11, s = m & (SEQ - 1);
                const int h = n0 >> 6;
                const size_t base = ((size_t)(b * NH + h) * SEQ + s) * HD;
                #pragma unroll
                for (int ni = 0; ni < 8; ni++) {
                    const int nloc = ni * 8 + qc * 2;
                    const int ng = n0 + nloc;
                    *(__half2*)(OutH + base + nloc) = __floats2half2_rn(
                        acc[mi][ni][half*2+0] + bias[ng],
                        acc[mi][ni][half*2+1] + bias[ng + 1]);
                }
            } else {
                float* dst = Out + (size_t)m * DM;
                #pragma unroll
                for (int ni = 0; ni < 8; ni++) {
                    const int ng = n0 + ni * 8 + qc * 2;
                    float2 o;
                    o.x = acc[mi][ni][half*2+0] + bias[ng];
                    o.y = acc[mi][ni][half*2+1] + bias[ng + 1];
                    *(float2*)(dst + ng) = o;
                }
            }
        }
    }
}

// ---------------- fp16 tensor-core flash attention ----------------
// grid (SEQ/128, NB*NH), 256 threads. Q in regs; K/V single fp16 in cp.async
// double-buffered 64x64 tiles. 1 MMA per output fragment everywhere.
#define ASTG 16384   // stage stride: K 8K + V 8K
__global__ __launch_bounds__(256, 1) void attn_tc(const uint32_t* __restrict__ maskw)
{
    extern __shared__ char smb[];
    const uint32_t sb = smem_u32(smb);
    const int tid = threadIdx.x, w = tid >> 5, lane = tid & 31;
    const int bh = blockIdx.y, q0 = blockIdx.x * 128;
    const int r = lane >> 2, qc2 = (lane & 3) * 2;
    const float SC = 0.125f * 1.44269504f;

    // ---- stage Q tile, pull fragments to regs ----
    {
        const __half* Q = g_Qh + ((size_t)bh * SEQ + q0) * HD;
        const int row = tid >> 1, cg = (tid & 1) * 4;
        #pragma unroll
        for (int c = 0; c < 4; c++) {
            const uint32_t off = sw128((uint32_t)(row * 128 + (cg + c) * 16));
            *(uint4*)(smb + off) = ((const uint4*)(Q + row * HD))[cg + c];
        }
    }
    __syncthreads();
    uint32_t qh[4][4];
    {
        const int row = w * 16 + ((lane >> 3) & 1) * 8 + (lane & 7);
        #pragma unroll
        for (int kc = 0; kc < 4; kc++) {
            const int chunk = kc * 2 + (lane >> 4);
            ldsm_x4(sb + sw128((uint32_t)(row * 128 + chunk * 16)), qh[kc]);
        }
    }
    __syncthreads();

    float ctx[8][4];
    #pragma unroll
    for (int j = 0; j < 8; j++)
        #pragma unroll
        for (int e = 0; e < 4; e++) ctx[j][e] = 0.f;
    float lsum0 = 0.f, lsum1 = 0.f;

    const __half* Kp = g_Kh + (size_t)bh * SEQ * HD;
    const __half* Vp = g_Vh + (size_t)bh * SEQ * HD;
    const uint32_t* mrow0 = maskw + ((size_t)bh * SEQ + (q0 + w * 16 + r)) * SEQ;
    const uint32_t* mrow1 = mrow0 + (size_t)8 * SEQ;

    // tile loader: K/V, 64 rows x 8 chunks each; 256 threads -> 2 per row, 4 chunks
    auto load_tile = [&](int kt, int buf) {
        const int arr = tid >> 7;                 // 0 = K, 1 = V
        const int row = (tid >> 1) & 63;
        const int cg  = (tid & 1) * 4;
        const __half* src = (arr == 0 ? Kp : Vp) + ((size_t)(kt * 64 + row)) * HD;
        const uint32_t dstb = sb + buf * ASTG + arr * 8192;
        #pragma unroll
        for (int c = 0; c < 4; c++) {
            cpasync16(dstb + sw128((uint32_t)(row * 128 + (cg + c) * 16)),
                      (const uint4*)src + cg + c);
        }
        cp_commit();
    };

    load_tile(0, 0);

    for (int kt = 0; kt < SEQ / 64; kt++) {
        if (kt < SEQ / 64 - 1) { load_tile(kt + 1, (kt + 1) & 1); cp_wait1(); }
        else cp_wait0();
        __syncthreads();
        const uint32_t base = sb + (kt & 1) * ASTG;

        // ---- S = Q K^T ----
        float sacc[8][4];
        #pragma unroll
        for (int j = 0; j < 8; j++) {
            #pragma unroll
            for (int e = 0; e < 4; e++) sacc[j][e] = 0.f;
            uint32_t kb[8];
            #pragma unroll
            for (int half = 0; half < 2; half++) {
                const int row = j * 8 + (lane & 7);
                const int chunk = half * 4 + (lane >> 3);
                ldsm_x4(base + sw128((uint32_t)(row * 128 + chunk * 16)), kb + half * 4);
            }
            #pragma unroll
            for (int kc = 0; kc < 4; kc++) {
                const int i0 = (kc >> 1) * 4 + (kc & 1) * 2;
                mma16816(sacc[j], qh[kc], kb[i0], kb[i0 + 1]);
            }
        }

        // ---- mask + exp + pack P ----
        uint32_t pf[4][4];
        const int kb = kt * 64;
        #pragma unroll
        for (int j = 0; j < 8; j++) {
            uint2 m0 = *(const uint2*)(mrow0 + kb + j * 8 + qc2);
            uint2 m1 = *(const uint2*)(mrow1 + kb + j * 8 + qc2);
            float p0 = m0.x ? fexp2(sacc[j][0] * SC) : 0.f;
            float p1 = m0.y ? fexp2(sacc[j][1] * SC) : 0.f;
            float p2 = m1.x ? fexp2(sacc[j][2] * SC) : 0.f;
            float p3 = m1.y ? fexp2(sacc[j][3] * SC) : 0.f;
            lsum0 += p0 + p1;
            lsum1 += p2 + p3;
            pf[j >> 1][(j & 1) * 2 + 0] = packh(p0, p1);
            pf[j >> 1][(j & 1) * 2 + 1] = packh(p2, p3);
        }

        // ---- ctx += P V ----
        #pragma unroll
        for (int kc = 0; kc < 4; kc++) {
            #pragma unroll
            for (int dp = 0; dp < 4; dp++) {
                const int row = kc * 16 + ((lane >> 3) & 1) * 8 + (lane & 7);
                const int chunk = dp * 2 + (lane >> 4);
                uint32_t vb[4];
                ldsm_x4t(base + 8192 + sw128((uint32_t)(row * 128 + chunk * 16)), vb);
                mma16816(ctx[dp*2],   pf[kc], vb[0], vb[1]);
                mma16816(ctx[dp*2+1], pf[kc], vb[2], vb[3]);
            }
        }
        __syncthreads();
    }

    // ---- normalize + write ctx (fp16) into [b, s, h*64+d] ----
    lsum0 += __shfl_xor_sync(0xffffffffu, lsum0, 1);
    lsum0 += __shfl_xor_sync(0xffffffffu, lsum0, 2);
    lsum1 += __shfl_xor_sync(0xffffffffu, lsum1, 1);
    lsum1 += __shfl_xor_sync(0xffffffffu, lsum1, 2);
    const float inv0 = (lsum0 > 0.f) ? 1.f / lsum0 : 0.f;
    const float inv1 = (lsum1 > 0.f) ? 1.f / lsum1 : 0.f;
    const int b = bh >> 4, h = bh & (NH - 1);
    const int s0 = q0 + w * 16 + r;
    const size_t base0 = ((size_t)b * SEQ + s0) * DM + h * 64;
    const size_t base1 = base0 + (size_t)8 * DM;
    #pragma unroll
    for (int j = 0; j < 8; j++) {
        const int d = j * 8 + qc2;
        *(__half2*)(g_ch + base0 + d) =
            __floats2half2_rn(ctx[j][0] * inv0, ctx[j][1] * inv0);
        *(__half2*)(g_ch + base1 + d) =
            __floats2half2_rn(ctx[j][2] * inv1, ctx[j][3] * inv1);
    }
}

// ---------------- launch ----------------
extern "C" void kernel_launch(void* const* d_in, const int* in_sizes, int n_in,
                              void* d_out, int out_size)
{
    const float* x  = (const float*)d_in[0];
    const uint32_t* maskw = (const uint32_t*)d_in[1];
    const float* Wq = (const float*)d_in[2];
    const float* bq = (const float*)d_in[3];
    const float* Wk = (const float*)d_in[4];
    const float* bk = (const float*)d_in[5];
    const float* Wv = (const float*)d_in[6];
    const float* bv = (const float*)d_in[7];
    const float* Wo = (const float*)d_in[8];
    const float* bo = (const float*)d_in[9];
    float* out = (float*)d_out;

    __half *xh, *ch, *wqh, *wkh, *wvh, *woh, *qh, *kh, *vh;
    cudaGetSymbolAddress((void**)&xh,  g_xh);
    cudaGetSymbolAddress((void**)&ch,  g_ch);
    cudaGetSymbolAddress((void**)&wqh, g_wqh);
    cudaGetSymbolAddress((void**)&wkh, g_wkh);
    cudaGetSymbolAddress((void**)&wvh, g_wvh);
    cudaGetSymbolAddress((void**)&woh, g_woh);
    cudaGetSymbolAddress((void**)&qh,  g_Qh);
    cudaGetSymbolAddress((void**)&kh,  g_Kh);
    cudaGetSymbolAddress((void**)&vh,  g_Vh);

    const int GEMM_SMEM = 2 * GSTG;   // 32768
    const int ATTN_SMEM = 2 * ASTG;   // 32768
    cudaFuncSetAttribute(gemm_tc<0>, cudaFuncAttributeMaxDynamicSharedMemorySize, GEMM_SMEM);
    cudaFuncSetAttribute(gemm_tc<1>, cudaFuncAttributeMaxDynamicSharedMemorySize, GEMM_SMEM);
    cudaFuncSetAttribute(gemm_tc<2>, cudaFuncAttributeMaxDynamicSharedMemorySize, GEMM_SMEM);
    cudaFuncSetAttribute(gemm_tc<3>, cudaFuncAttributeMaxDynamicSharedMemorySize, GEMM_SMEM);
    cudaFuncSetAttribute(attn_tc,    cudaFuncAttributeMaxDynamicSharedMemorySize, ATTN_SMEM);

    const int nx4 = (int)((size_t)MTOT * DM / 4);
    const int nw4 = (int)((size_t)DM * DM / 4);
    conv_s<<<nx4/256, 256>>>((const float4*)x,  (__half2*)xh,  nx4);
    conv_s<<<nw4/256, 256>>>((const float4*)Wq, (__half2*)wqh, nw4);
    conv_s<<<nw4/256, 256>>>((const float4*)Wk, (__half2*)wkh, nw4);
    conv_s<<<nw4/256, 256>>>((const float4*)Wv, (__half2*)wvh, nw4);
    conv_s<<<nw4/256, 256>>>((const float4*)Wo, (__half2*)woh, nw4);

    dim3 ggrid(DM / 128, MTOT / 128);   // (8, 32)
    gemm_tc<0><<<ggrid, 256, GEMM_SMEM>>>(xh, wqh, bq, qh, nullptr);
    gemm_tc<1><<<ggrid, 256, GEMM_SMEM>>>(xh, wkh, bk, kh, nullptr);
    gemm_tc<2><<<ggrid, 256, GEMM_SMEM>>>(xh, wvh, bv, vh, nullptr);

    dim3 agrid(SEQ / 128, NB * NH);     // (16, 32)
    attn_tc<<<agrid, 256, ATTN_SMEM>>>(maskw);

    gemm_tc<3><<<ggrid, 256, GEMM_SMEM>>>(ch, woh, bo, nullptr, out);
}

// round 8
// speedup vs baseline: 6.2816x; 1.1798x over previous
#include <cuda_runtime.h>
#include <cuda_fp16.h>
#include <math.h>
#include <stdint.h>

#define NH   16
#define HD   64
#define NB   2
#define SEQ  2048
#define DM   1024
#define MTOT (NB*SEQ)

// ---------------- device scratch (allocation-free rule) ----------------
__device__ __align__(256) __half g_Qh[(size_t)NB*NH*SEQ*HD];
__device__ __align__(256) __half g_Kh[(size_t)NB*NH*SEQ*HD];
__device__ __align__(256) __half g_Vh[(size_t)NB*NH*SEQ*HD];
__device__ __align__(256) __half g_xh[(size_t)MTOT*DM];
__device__ __align__(256) __half g_ch[(size_t)MTOT*DM];
__device__ __align__(256) __half g_w4[4][(size_t)DM*DM];   // Wq, Wk, Wv, Wo fp16

// ---------------- helpers ----------------
__device__ __forceinline__ uint32_t smem_u32(const void* p) {
    uint32_t a;
    asm("{ .reg .u64 t; cvta.to.shared.u64 t, %1; cvt.u32.u64 %0, t; }" : "=r"(a) : "l"(p));
    return a;
}
__device__ __forceinline__ uint32_t sw128(uint32_t o) {   // 128B rows
    return o ^ (((o >> 7) & 7u) << 4);
}
__device__ __forceinline__ uint32_t sw64(uint32_t o) {    // 64B rows
    return o ^ (((o >> 7) & 3u) << 4);
}
__device__ __forceinline__ void cpasync16(uint32_t dst, const void* src) {
    asm volatile("cp.async.cg.shared.global [%0], [%1], 16;" :: "r"(dst), "l"(src));
}
__device__ __forceinline__ void cp_commit() {
    asm volatile("cp.async.commit_group;" ::: "memory");
}
__device__ __forceinline__ void cp_wait1() {
    asm volatile("cp.async.wait_group 1;" ::: "memory");
}
__device__ __forceinline__ void cp_wait0() {
    asm volatile("cp.async.wait_group 0;" ::: "memory");
}
__device__ __forceinline__ void ldsm_x4(uint32_t a, uint32_t* r) {
    asm volatile("ldmatrix.sync.aligned.m8n8.x4.shared.b16 {%0,%1,%2,%3}, [%4];"
                 : "=r"(r[0]), "=r"(r[1]), "=r"(r[2]), "=r"(r[3]) : "r"(a));
}
__device__ __forceinline__ void ldsm_x4t(uint32_t a, uint32_t* r) {
    asm volatile("ldmatrix.sync.aligned.m8n8.x4.trans.shared.b16 {%0,%1,%2,%3}, [%4];"
                 : "=r"(r[0]), "=r"(r[1]), "=r"(r[2]), "=r"(r[3]) : "r"(a));
}
__device__ __forceinline__ void mma16816(float* c, const uint32_t* a,
                                         uint32_t b0, uint32_t b1) {
    asm volatile(
        "mma.sync.aligned.m16n8k16.row.col.f32.f16.f16.f32 "
        "{%0,%1,%2,%3}, {%4,%5,%6,%7}, {%8,%9}, {%0,%1,%2,%3};"
        : "+f"(c[0]), "+f"(c[1]), "+f"(c[2]), "+f"(c[3])
        : "r"(a[0]), "r"(a[1]), "r"(a[2]), "r"(a[3]), "r"(b0), "r"(b1));
}
// FMA-only 2^e (no MUFU), e pre-multiplied by log2
__device__ __forceinline__ float fexp2(float e) {
    float t = e + 12582912.0f;
    int   ib = __float_as_int(t);
    float r = t - 12582912.0f;
    float f = e - r;
    float p = 1.3333558e-3f;
    p = fmaf(p, f, 9.6181291e-3f);
    p = fmaf(p, f, 5.5504109e-2f);
    p = fmaf(p, f, 2.4022651e-1f);
    p = fmaf(p, f, 6.9314718e-1f);
    p = fmaf(p, f, 1.0f);
    return __int_as_float((ib + (127 - 0x4B400000)) << 23) * p;
}
__device__ __forceinline__ uint32_t packh(float lo, float hi) {
    __half2 h = __floats2half2_rn(lo, hi);
    return *(uint32_t*)&h;
}

// ---------------- conversions fp32 -> fp16 ----------------
__global__ __launch_bounds__(256) void conv_s(const float4* __restrict__ src,
                                              __half2* __restrict__ dst, int n4) {
    int i = blockIdx.x * 256 + threadIdx.x;
    if (i >= n4) return;
    float4 v = src[i];
    dst[2*i]   = __floats2half2_rn(v.x, v.y);
    dst[2*i+1] = __floats2half2_rn(v.z, v.w);
}
// all 4 weight matrices in one launch: grid.y picks the source
__global__ __launch_bounds__(256) void conv_w(const float4* __restrict__ w0,
                                              const float4* __restrict__ w1,
                                              const float4* __restrict__ w2,
                                              const float4* __restrict__ w3,
                                              int n4) {
    int i = blockIdx.x * 256 + threadIdx.x;
    if (i >= n4) return;
    const int s = blockIdx.y;
    const float4* src = (s == 0) ? w0 : (s == 1) ? w1 : (s == 2) ? w2 : w3;
    __half2* dst = (__half2*)g_w4[s];
    float4 v = src[i];
    dst[2*i]   = __floats2half2_rn(v.x, v.y);
    dst[2*i+1] = __floats2half2_rn(v.z, v.w);
}

// ---------------- fp16 GEMM: Out[M,N] = A[M,K]@B[N,K]^T + bias ------------
// CTA 128x128, 8 warps, BK=32, cp.async 3-stage pipeline (1 sync/iter).
// DST<=2: half out [b,h,s,d]; DST 3: fp32 rows.
#define GSTG 16384   // stage stride: A 8K + B 8K
template<int DST>
__global__ __launch_bounds__(256, 2)
void gemm_tc(const __half* __restrict__ A_, const __half* __restrict__ B_,
             const float* __restrict__ bias,
             __half* __restrict__ OutH, float* __restrict__ Out)
{
    extern __shared__ char smb[];
    const uint32_t sb = smem_u32(smb);
    const int tid = threadIdx.x;
    const int wid = tid >> 5;
    const int lid = tid & 31;
    const int wm = wid & 3;
    const int wn = wid >> 2;
    const int bm = blockIdx.y * 128;
    const int bn = blockIdx.x * 128;
    const int NIT = DM / 32;

    float acc[2][8][4];
    #pragma unroll
    for (int mi = 0; mi < 2; mi++)
        #pragma unroll
        for (int ni = 0; ni < 8; ni++)
            #pragma unroll
            for (int e = 0; e < 4; e++) acc[mi][ni][e] = 0.f;

    auto load_stage = [&](int c) {
        const uint32_t base = sb + (uint32_t)(c % 3) * GSTG;
        #pragma unroll
        for (int p = 0; p < 2; p++) {
            const int id = tid + p * 256;
            const int row = id >> 2, ch = id & 3;
            const uint32_t so = sw64((uint32_t)(row * 64 + ch * 16));
            const size_t ga = (size_t)(bm + row) * (DM / 8) + c * 4 + ch;
            const size_t gb = (size_t)(bn + row) * (DM / 8) + c * 4 + ch;
            cpasync16(base + so,        (const uint4*)A_ + ga);
            cpasync16(base + 8192 + so, (const uint4*)B_ + gb);
        }
        cp_commit();
    };

    load_stage(0);
    load_stage(1);

    for (int c = 0; c < NIT; c++) {
        if (c == NIT - 1) cp_wait0(); else cp_wait1();
        __syncthreads();

        const uint32_t base = sb + (uint32_t)(c % 3) * GSTG;
        #pragma unroll
        for (int ks = 0; ks < 2; ks++) {
            uint32_t ah[2][4];
            #pragma unroll
            for (int mi = 0; mi < 2; mi++) {
                const int row = wm * 32 + mi * 16 + (lid & 15);
                const int colb = (ks * 16 + (lid >> 4) * 8) * 2;
                ldsm_x4(base + sw64((uint32_t)(row * 64 + colb)), ah[mi]);
            }
            uint32_t bh[8][2];
            #pragma unroll
            for (int nj = 0; nj < 4; nj++) {
                const int row = wn * 64 + nj * 16 + ((lid >> 4) << 3) + (lid & 7);
                const int colb = (ks * 16 + ((lid >> 3) & 1) * 8) * 2;
                uint32_t t[4];
                ldsm_x4(base + 8192 + sw64((uint32_t)(row * 64 + colb)), t);
                bh[nj*2][0] = t[0]; bh[nj*2][1] = t[1];
                bh[nj*2+1][0] = t[2]; bh[nj*2+1][1] = t[3];
            }
            #pragma unroll
            for (int mi = 0; mi < 2; mi++)
                #pragma unroll
                for (int ni = 0; ni < 8; ni++)
                    mma16816(acc[mi][ni], ah[mi], bh[ni][0], bh[ni][1]);
        }
        if (c + 2 < NIT) load_stage(c + 2);
    }

    const int qr = lid >> 2, qc = lid & 3;
    #pragma unroll
    for (int mi = 0; mi < 2; mi++) {
        #pragma unroll
        for (int half = 0; half < 2; half++) {
            const int m = bm + wm * 32 + mi * 16 + half * 8 + qr;
            const int n0 = bn + wn * 64;
            if (DST <= 2) {
                const int b = m >> 11, s = m & (SEQ - 1);
                const int h = n0 >> 6;
                const size_t base = ((size_t)(b * NH + h) * SEQ + s) * HD;
                #pragma unroll
                for (int ni = 0; ni < 8; ni++) {
                    const int nloc = ni * 8 + qc * 2;
                    const int ng = n0 + nloc;
                    *(__half2*)(OutH + base + nloc) = __floats2half2_rn(
                        acc[mi][ni][half*2+0] + bias[ng],
                        acc[mi][ni][half*2+1] + bias[ng + 1]);
                }
            } else {
                float* dst = Out + (size_t)m * DM;
                #pragma unroll
                for (int ni = 0; ni < 8; ni++) {
                    const int ng = n0 + ni * 8 + qc * 2;
                    float2 o;
                    o.x = acc[mi][ni][half*2+0] + bias[ng];
                    o.y = acc[mi][ni][half*2+1] + bias[ng + 1];
                    *(float2*)(dst + ng) = o;
                }
            }
        }
    }
}

// ---------------- fp16 tensor-core flash attention ----------------
// grid (SEQ/128, NB*NH), 256 threads, 2 CTAs/SM. Q in regs; K/V fp16 in
// cp.async 3-stage 64x64 tiles (1 sync/iter).
#define ASTG 16384   // stage stride: K 8K + V 8K
__global__ __launch_bounds__(256, 2) void attn_tc(const uint32_t* __restrict__ maskw)
{
    extern __shared__ char smb[];
    const uint32_t sb = smem_u32(smb);
    const int tid = threadIdx.x, w = tid >> 5, lane = tid & 31;
    const int bh = blockIdx.y, q0 = blockIdx.x * 128;
    const int r = lane >> 2, qc2 = (lane & 3) * 2;
    const float SC = 0.125f * 1.44269504f;
    const int NT = SEQ / 64;

    // ---- stage Q tile (buf 0 area), pull fragments, then start pipeline ----
    {
        const __half* Q = g_Qh + ((size_t)bh * SEQ + q0) * HD;
        const int row = tid >> 1, cg = (tid & 1) * 4;
        #pragma unroll
        for (int c = 0; c < 4; c++) {
            const uint32_t off = sw128((uint32_t)(row * 128 + (cg + c) * 16));
            *(uint4*)(smb + off) = ((const uint4*)(Q + row * HD))[cg + c];
        }
    }
    __syncthreads();
    uint32_t qh[4][4];
    {
        const int row = w * 16 + ((lane >> 3) & 1) * 8 + (lane & 7);
        #pragma unroll
        for (int kc = 0; kc < 4; kc++) {
            const int chunk = kc * 2 + (lane >> 4);
            ldsm_x4(sb + sw128((uint32_t)(row * 128 + chunk * 16)), qh[kc]);
        }
    }
    __syncthreads();

    float ctx[8][4];
    #pragma unroll
    for (int j = 0; j < 8; j++)
        #pragma unroll
        for (int e = 0; e < 4; e++) ctx[j][e] = 0.f;
    float lsum0 = 0.f, lsum1 = 0.f;

    const __half* Kp = g_Kh + (size_t)bh * SEQ * HD;
    const __half* Vp = g_Vh + (size_t)bh * SEQ * HD;
    const uint32_t* mrow0 = maskw + ((size_t)bh * SEQ + (q0 + w * 16 + r)) * SEQ;
    const uint32_t* mrow1 = mrow0 + (size_t)8 * SEQ;

    auto load_tile = [&](int kt) {
        const int arr = tid >> 7;                 // 0 = K, 1 = V
        const int row = (tid >> 1) & 63;
        const int cg  = (tid & 1) * 4;
        const __half* src = (arr == 0 ? Kp : Vp) + ((size_t)(kt * 64 + row)) * HD;
        const uint32_t dstb = sb + (uint32_t)(kt % 3) * ASTG + arr * 8192;
        #pragma unroll
        for (int c = 0; c < 4; c++) {
            cpasync16(dstb + sw128((uint32_t)(row * 128 + (cg + c) * 16)),
                      (const uint4*)src + cg + c);
        }
        cp_commit();
    };

    load_tile(0);
    load_tile(1);

    for (int kt = 0; kt < NT; kt++) {
        if (kt == NT - 1) cp_wait0(); else cp_wait1();
        __syncthreads();
        const uint32_t base = sb + (uint32_t)(kt % 3) * ASTG;

        // ---- S = Q K^T ----
        float sacc[8][4];
        #pragma unroll
        for (int j = 0; j < 8; j++) {
            #pragma unroll
            for (int e = 0; e < 4; e++) sacc[j][e] = 0.f;
            uint32_t kb[8];
            #pragma unroll
            for (int half = 0; half < 2; half++) {
                const int row = j * 8 + (lane & 7);
                const int chunk = half * 4 + (lane >> 3);
                ldsm_x4(base + sw128((uint32_t)(row * 128 + chunk * 16)), kb + half * 4);
            }
            #pragma unroll
            for (int kc = 0; kc < 4; kc++) {
                const int i0 = (kc >> 1) * 4 + (kc & 1) * 2;
                mma16816(sacc[j], qh[kc], kb[i0], kb[i0 + 1]);
            }
        }

        // ---- mask + exp + pack P ----
        uint32_t pf[4][4];
        const int kb = kt * 64;
        #pragma unroll
        for (int j = 0; j < 8; j++) {
            uint2 m0 = *(const uint2*)(mrow0 + kb + j * 8 + qc2);
            uint2 m1 = *(const uint2*)(mrow1 + kb + j * 8 + qc2);
            float p0 = m0.x ? fexp2(sacc[j][0] * SC) : 0.f;
            float p1 = m0.y ? fexp2(sacc[j][1] * SC) : 0.f;
            float p2 = m1.x ? fexp2(sacc[j][2] * SC) : 0.f;
            float p3 = m1.y ? fexp2(sacc[j][3] * SC) : 0.f;
            lsum0 += p0 + p1;
            lsum1 += p2 + p3;
            pf[j >> 1][(j & 1) * 2 + 0] = packh(p0, p1);
            pf[j >> 1][(j & 1) * 2 + 1] = packh(p2, p3);
        }

        // ---- ctx += P V ----
        #pragma unroll
        for (int kc = 0; kc < 4; kc++) {
            #pragma unroll
            for (int dp = 0; dp < 4; dp++) {
                const int row = kc * 16 + ((lane >> 3) & 1) * 8 + (lane & 7);
                const int chunk = dp * 2 + (lane >> 4);
                uint32_t vb[4];
                ldsm_x4t(base + 8192 + sw128((uint32_t)(row * 128 + chunk * 16)), vb);
                mma16816(ctx[dp*2],   pf[kc], vb[0], vb[1]);
                mma16816(ctx[dp*2+1], pf[kc], vb[2], vb[3]);
            }
        }
        if (kt + 2 < NT) load_tile(kt + 2);
    }

    // ---- normalize + write ctx (fp16) into [b, s, h*64+d] ----
    lsum0 += __shfl_xor_sync(0xffffffffu, lsum0, 1);
    lsum0 += __shfl_xor_sync(0xffffffffu, lsum0, 2);
    lsum1 += __shfl_xor_sync(0xffffffffu, lsum1, 1);
    lsum1 += __shfl_xor_sync(0xffffffffu, lsum1, 2);
    const float inv0 = (lsum0 > 0.f) ? 1.f / lsum0 : 0.f;
    const float inv1 = (lsum1 > 0.f) ? 1.f / lsum1 : 0.f;
    const int b = bh >> 4, h = bh & (NH - 1);
    const int s0 = q0 + w * 16 + r;
    const size_t base0 = ((size_t)b * SEQ + s0) * DM + h * 64;
    const size_t base1 = base0 + (size_t)8 * DM;
    #pragma unroll
    for (int j = 0; j < 8; j++) {
        const int d = j * 8 + qc2;
        *(__half2*)(g_ch + base0 + d) =
            __floats2half2_rn(ctx[j][0] * inv0, ctx[j][1] * inv0);
        *(__half2*)(g_ch + base1 + d) =
            __floats2half2_rn(ctx[j][2] * inv1, ctx[j][3] * inv1);
    }
}

// ---------------- launch ----------------
extern "C" void kernel_launch(void* const* d_in, const int* in_sizes, int n_in,
                              void* d_out, int out_size)
{
    const float* x  = (const float*)d_in[0];
    const uint32_t* maskw = (const uint32_t*)d_in[1];
    const float* Wq = (const float*)d_in[2];
    const float* bq = (const float*)d_in[3];
    const float* Wk = (const float*)d_in[4];
    const float* bk = (const float*)d_in[5];
    const float* Wv = (const float*)d_in[6];
    const float* bv = (const float*)d_in[7];
    const float* Wo = (const float*)d_in[8];
    const float* bo = (const float*)d_in[9];
    float* out = (float*)d_out;

    __half *xh, *ch, *qh, *kh, *vh, *w4;
    cudaGetSymbolAddress((void**)&xh, g_xh);
    cudaGetSymbolAddress((void**)&ch, g_ch);
    cudaGetSymbolAddress((void**)&qh, g_Qh);
    cudaGetSymbolAddress((void**)&kh, g_Kh);
    cudaGetSymbolAddress((void**)&vh, g_Vh);
    cudaGetSymbolAddress((void**)&w4, g_w4);

    const int GEMM_SMEM = 3 * GSTG;   // 49152
    const int ATTN_SMEM = 3 * ASTG;   // 49152
    cudaFuncSetAttribute(gemm_tc<0>, cudaFuncAttributeMaxDynamicSharedMemorySize, GEMM_SMEM);
    cudaFuncSetAttribute(gemm_tc<1>, cudaFuncAttributeMaxDynamicSharedMemorySize, GEMM_SMEM);
    cudaFuncSetAttribute(gemm_tc<2>, cudaFuncAttributeMaxDynamicSharedMemorySize, GEMM_SMEM);
    cudaFuncSetAttribute(gemm_tc<3>, cudaFuncAttributeMaxDynamicSharedMemorySize, GEMM_SMEM);
    cudaFuncSetAttribute(attn_tc,    cudaFuncAttributeMaxDynamicSharedMemorySize, ATTN_SMEM);

    const int nx4 = (int)((size_t)MTOT * DM / 4);
    const int nw4 = (int)((size_t)DM * DM / 4);
    conv_s<<<nx4/256, 256>>>((const float4*)x, (__half2*)xh, nx4);
    dim3 wgrid(nw4/256, 4);
    conv_w<<<wgrid, 256>>>((const float4*)Wq, (const float4*)Wk,
                           (const float4*)Wv, (const float4*)Wo, nw4);

    __half* wqh = w4;
    __half* wkh = w4 + (size_t)DM * DM;
    __half* wvh = w4 + (size_t)2 * DM * DM;
    __half* woh = w4 + (size_t)3 * DM * DM;

    dim3 ggrid(DM / 128, MTOT / 128);   // (8, 32)
    gemm_tc<0><<<ggrid, 256, GEMM_SMEM>>>(xh, wqh, bq, qh, nullptr);
    gemm_tc<1><<<ggrid, 256, GEMM_SMEM>>>(xh, wkh, bk, kh, nullptr);
    gemm_tc<2><<<ggrid, 256, GEMM_SMEM>>>(xh, wvh, bv, vh, nullptr);

    dim3 agrid(SEQ / 128, NB * NH);     // (16, 32)
    attn_tc<<<agrid, 256, ATTN_SMEM>>>(maskw);

    gemm_tc<3><<<ggrid, 256, GEMM_SMEM>>>(ch, woh, bo, nullptr, out);
}

// round 9
// speedup vs baseline: 9.0384x; 1.4389x over previous
#include <cuda_runtime.h>
#include <cuda_fp16.h>
#include <math.h>
#include <stdint.h>

#define NH   16
#define HD   64
#define NB   2
#define SEQ  2048
#define DM   1024
#define MTOT (NB*SEQ)

// ---------------- device scratch (allocation-free rule) ----------------
__device__ __align__(256) __half g_Qh[(size_t)NB*NH*SEQ*HD];
__device__ __align__(256) __half g_Kh[(size_t)NB*NH*SEQ*HD];
__device__ __align__(256) __half g_Vh[(size_t)NB*NH*SEQ*HD];
__device__ __align__(256) __half g_xh[(size_t)MTOT*DM];
__device__ __align__(256) __half g_ch[(size_t)MTOT*DM];
__device__ __align__(256) __half g_w4[4][(size_t)DM*DM];   // Wq, Wk, Wv, Wo fp16

// ---------------- helpers ----------------
__device__ __forceinline__ uint32_t smem_u32(const void* p) {
    uint32_t a;
    asm("{ .reg .u64 t; cvta.to.shared.u64 t, %1; cvt.u32.u64 %0, t; }" : "=r"(a) : "l"(p));
    return a;
}
__device__ __forceinline__ uint32_t sw128(uint32_t o) {   // 128B rows
    return o ^ (((o >> 7) & 7u) << 4);
}
__device__ __forceinline__ uint32_t sw64(uint32_t o) {    // 64B rows
    return o ^ (((o >> 7) & 3u) << 4);
}
__device__ __forceinline__ void cpasync16(uint32_t dst, const void* src) {
    asm volatile("cp.async.cg.shared.global [%0], [%1], 16;" :: "r"(dst), "l"(src));
}
__device__ __forceinline__ void cp_commit() {
    asm volatile("cp.async.commit_group;" ::: "memory");
}
__device__ __forceinline__ void cp_wait1() {
    asm volatile("cp.async.wait_group 1;" ::: "memory");
}
__device__ __forceinline__ void cp_wait0() {
    asm volatile("cp.async.wait_group 0;" ::: "memory");
}
__device__ __forceinline__ void ldsm_x4(uint32_t a, uint32_t* r) {
    asm volatile("ldmatrix.sync.aligned.m8n8.x4.shared.b16 {%0,%1,%2,%3}, [%4];"
                 : "=r"(r[0]), "=r"(r[1]), "=r"(r[2]), "=r"(r[3]) : "r"(a));
}
__device__ __forceinline__ void ldsm_x4t(uint32_t a, uint32_t* r) {
    asm volatile("ldmatrix.sync.aligned.m8n8.x4.trans.shared.b16 {%0,%1,%2,%3}, [%4];"
                 : "=r"(r[0]), "=r"(r[1]), "=r"(r[2]), "=r"(r[3]) : "r"(a));
}
__device__ __forceinline__ void mma16816(float* c, const uint32_t* a,
                                         uint32_t b0, uint32_t b1) {
    asm volatile(
        "mma.sync.aligned.m16n8k16.row.col.f32.f16.f16.f32 "
        "{%0,%1,%2,%3}, {%4,%5,%6,%7}, {%8,%9}, {%0,%1,%2,%3};"
        : "+f"(c[0]), "+f"(c[1]), "+f"(c[2]), "+f"(c[3])
        : "r"(a[0]), "r"(a[1]), "r"(a[2]), "r"(a[3]), "r"(b0), "r"(b1));
}
// MUFU 2^x — attention is issue-bound, MUFU pipe has ample headroom here
__device__ __forceinline__ float ex2f(float e) {
    float r;
    asm("ex2.approx.f32 %0, %1;" : "=f"(r) : "f"(e));
    return r;
}
__device__ __forceinline__ uint32_t packh(float lo, float hi) {
    __half2 h = __floats2half2_rn(lo, hi);
    return *(uint32_t*)&h;
}

// ---------------- conversions fp32 -> fp16 ----------------
__global__ __launch_bounds__(256) void conv_s(const float4* __restrict__ src,
                                              __half2* __restrict__ dst, int n4) {
    int i = blockIdx.x * 256 + threadIdx.x;
    if (i >= n4) return;
    float4 v = src[i];
    dst[2*i]   = __floats2half2_rn(v.x, v.y);
    dst[2*i+1] = __floats2half2_rn(v.z, v.w);
}
__global__ __launch_bounds__(256) void conv_w(const float4* __restrict__ w0,
                                              const float4* __restrict__ w1,
                                              const float4* __restrict__ w2,
                                              const float4* __restrict__ w3,
                                              int n4) {
    int i = blockIdx.x * 256 + threadIdx.x;
    if (i >= n4) return;
    const int s = blockIdx.y;
    const float4* src = (s == 0) ? w0 : (s == 1) ? w1 : (s == 2) ? w2 : w3;
    __half2* dst = (__half2*)g_w4[s];
    float4 v = src[i];
    dst[2*i]   = __floats2half2_rn(v.x, v.y);
    dst[2*i+1] = __floats2half2_rn(v.z, v.w);
}

// ---------------- shared GEMM mainloop (CTA 128x128, BK=32, 3-stage) ------
#define GSTG 16384   // stage stride: A 8K + B 8K

struct GemmCore {
    uint32_t sb;
    int tid, wid, lid, wm, wn, bm, bn;
    float acc[2][8][4];

    __device__ __forceinline__ void init(uint32_t sb_, int bm_, int bn_) {
        sb = sb_; tid = threadIdx.x; wid = tid >> 5; lid = tid & 31;
        wm = wid & 3; wn = wid >> 2; bm = bm_; bn = bn_;
        #pragma unroll
        for (int mi = 0; mi < 2; mi++)
            #pragma unroll
            for (int ni = 0; ni < 8; ni++)
                #pragma unroll
                for (int e = 0; e < 4; e++) acc[mi][ni][e] = 0.f;
    }
    __device__ __forceinline__ void load_stage(const __half* A_, const __half* B_,
                                               char* smb, int c) {
        const uint32_t base = sb + (uint32_t)(c % 3) * GSTG;
        #pragma unroll
        for (int p = 0; p < 2; p++) {
            const int id = tid + p * 256;
            const int row = id >> 2, ch = id & 3;
            const uint32_t so = sw64((uint32_t)(row * 64 + ch * 16));
            const size_t ga = (size_t)(bm + row) * (DM / 8) + c * 4 + ch;
            const size_t gb = (size_t)(bn + row) * (DM / 8) + c * 4 + ch;
            cpasync16(base + so,        (const uint4*)A_ + ga);
            cpasync16(base + 8192 + so, (const uint4*)B_ + gb);
        }
        cp_commit();
    }
    __device__ __forceinline__ void mainloop(const __half* A_, const __half* B_,
                                             char* smb) {
        const int NIT = DM / 32;
        load_stage(A_, B_, smb, 0);
        load_stage(A_, B_, smb, 1);
        for (int c = 0; c < NIT; c++) {
            if (c == NIT - 1) cp_wait0(); else cp_wait1();
            __syncthreads();
            const uint32_t base = sb + (uint32_t)(c % 3) * GSTG;
            #pragma unroll
            for (int ks = 0; ks < 2; ks++) {
                uint32_t ah[2][4];
                #pragma unroll
                for (int mi = 0; mi < 2; mi++) {
                    const int row = wm * 32 + mi * 16 + (lid & 15);
                    const int colb = (ks * 16 + (lid >> 4) * 8) * 2;
                    ldsm_x4(base + sw64((uint32_t)(row * 64 + colb)), ah[mi]);
                }
                uint32_t bh[8][2];
                #pragma unroll
                for (int nj = 0; nj < 4; nj++) {
                    const int row = wn * 64 + nj * 16 + ((lid >> 4) << 3) + (lid & 7);
                    const int colb = (ks * 16 + ((lid >> 3) & 1) * 8) * 2;
                    uint32_t t[4];
                    ldsm_x4(base + 8192 + sw64((uint32_t)(row * 64 + colb)), t);
                    bh[nj*2][0] = t[0]; bh[nj*2][1] = t[1];
                    bh[nj*2+1][0] = t[2]; bh[nj*2+1][1] = t[3];
                }
                #pragma unroll
                for (int mi = 0; mi < 2; mi++)
                    #pragma unroll
                    for (int ni = 0; ni < 8; ni++)
                        mma16816(acc[mi][ni], ah[mi], bh[ni][0], bh[ni][1]);
            }
            if (c + 2 < NIT) load_stage(A_, B_, smb, c + 2);
        }
    }
};

// QKV fused: blockIdx.z selects weight / bias / output. Output half [b,h,s,d].
__global__ __launch_bounds__(256, 2)
void gemm_qkv(const __half* __restrict__ A_,
              const float* __restrict__ bq, const float* __restrict__ bk,
              const float* __restrict__ bv)
{
    extern __shared__ char smb[];
    const int z = blockIdx.z;
    const __half* B_ = g_w4[z];
    const float* bias = (z == 0) ? bq : (z == 1) ? bk : bv;
    __half* OutH = (z == 0) ? g_Qh : (z == 1) ? g_Kh : g_Vh;

    GemmCore g;
    g.init(smem_u32(smb), blockIdx.y * 128, blockIdx.x * 128);
    g.mainloop(A_, B_, smb);

    const int qr = g.lid >> 2, qc = g.lid & 3;
    #pragma unroll
    for (int mi = 0; mi < 2; mi++) {
        #pragma unroll
        for (int half = 0; half < 2; half++) {
            const int m = g.bm + g.wm * 32 + mi * 16 + half * 8 + qr;
            const int n0 = g.bn + g.wn * 64;
            const int b = m >> 11, s = m & (SEQ - 1);
            const int h = n0 >> 6;
            const size_t base = ((size_t)(b * NH + h) * SEQ + s) * HD;
            #pragma unroll
            for (int ni = 0; ni < 8; ni++) {
                const int nloc = ni * 8 + qc * 2;
                const int ng = n0 + nloc;
                *(__half2*)(OutH + base + nloc) = __floats2half2_rn(
                    g.acc[mi][ni][half*2+0] + bias[ng],
                    g.acc[mi][ni][half*2+1] + bias[ng + 1]);
            }
        }
    }
}

// Output GEMM: fp32 row-major into d_out
__global__ __launch_bounds__(256, 2)
void gemm_o(const __half* __restrict__ A_, const float* __restrict__ bias,
            float* __restrict__ Out)
{
    extern __shared__ char smb[];
    GemmCore g;
    g.init(smem_u32(smb), blockIdx.y * 128, blockIdx.x * 128);
    g.mainloop(A_, g_w4[3], smb);

    const int qr = g.lid >> 2, qc = g.lid & 3;
    #pragma unroll
    for (int mi = 0; mi < 2; mi++) {
        #pragma unroll
        for (int half = 0; half < 2; half++) {
            const int m = g.bm + g.wm * 32 + mi * 16 + half * 8 + qr;
            const int n0 = g.bn + g.wn * 64;
            float* dst = Out + (size_t)m * DM;
            #pragma unroll
            for (int ni = 0; ni < 8; ni++) {
                const int ng = n0 + ni * 8 + qc * 2;
                float2 o;
                o.x = g.acc[mi][ni][half*2+0] + bias[ng];
                o.y = g.acc[mi][ni][half*2+1] + bias[ng + 1];
                *(float2*)(dst + ng) = o;
            }
        }
    }
}

// ---------------- fp16 tensor-core flash attention ----------------
// grid (SEQ/128, NB*NH), 256 threads, 2 CTAs/SM. Q in regs; K/V fp16 in
// cp.async 3-stage 64x64 tiles (1 sync/iter). exp via MUFU ex2.
#define ASTG 16384   // stage stride: K 8K + V 8K
__global__ __launch_bounds__(256, 2) void attn_tc(const uint32_t* __restrict__ maskw)
{
    extern __shared__ char smb[];
    const uint32_t sb = smem_u32(smb);
    const int tid = threadIdx.x, w = tid >> 5, lane = tid & 31;
    const int bh = blockIdx.y, q0 = blockIdx.x * 128;
    const int r = lane >> 2, qc2 = (lane & 3) * 2;
    const float SC = 0.125f * 1.44269504f;
    const int NT = SEQ / 64;

    // ---- stage Q tile, pull fragments, then start pipeline ----
    {
        const __half* Q = g_Qh + ((size_t)bh * SEQ + q0) * HD;
        const int row = tid >> 1, cg = (tid & 1) * 4;
        #pragma unroll
        for (int c = 0; c < 4; c++) {
            const uint32_t off = sw128((uint32_t)(row * 128 + (cg + c) * 16));
            *(uint4*)(smb + off) = ((const uint4*)(Q + row * HD))[cg + c];
        }
    }
    __syncthreads();
    uint32_t qh[4][4];
    {
        const int row = w * 16 + ((lane >> 3) & 1) * 8 + (lane & 7);
        #pragma unroll
        for (int kc = 0; kc < 4; kc++) {
            const int chunk = kc * 2 + (lane >> 4);
            ldsm_x4(sb + sw128((uint32_t)(row * 128 + chunk * 16)), qh[kc]);
        }
    }
    __syncthreads();

    float ctx[8][4];
    #pragma unroll
    for (int j = 0; j < 8; j++)
        #pragma unroll
        for (int e = 0; e < 4; e++) ctx[j][e] = 0.f;
    float lsum0 = 0.f, lsum1 = 0.f;

    const __half* Kp = g_Kh + (size_t)bh * SEQ * HD;
    const __half* Vp = g_Vh + (size_t)bh * SEQ * HD;
    const uint32_t* mrow0 = maskw + ((size_t)bh * SEQ + (q0 + w * 16 + r)) * SEQ;
    const uint32_t* mrow1 = mrow0 + (size_t)8 * SEQ;

    auto load_tile = [&](int kt) {
        const int arr = tid >> 7;                 // 0 = K, 1 = V
        const int row = (tid >> 1) & 63;
        const int cg  = (tid & 1) * 4;
        const __half* src = (arr == 0 ? Kp : Vp) + ((size_t)(kt * 64 + row)) * HD;
        const uint32_t dstb = sb + (uint32_t)(kt % 3) * ASTG + arr * 8192;
        #pragma unroll
        for (int c = 0; c < 4; c++) {
            cpasync16(dstb + sw128((uint32_t)(row * 128 + (cg + c) * 16)),
                      (const uint4*)src + cg + c);
        }
        cp_commit();
    };

    load_tile(0);
    load_tile(1);

    for (int kt = 0; kt < NT; kt++) {
        if (kt == NT - 1) cp_wait0(); else cp_wait1();
        __syncthreads();
        const uint32_t base = sb + (uint32_t)(kt % 3) * ASTG;

        // ---- S = Q K^T ----
        float sacc[8][4];
        #pragma unroll
        for (int j = 0; j < 8; j++) {
            #pragma unroll
            for (int e = 0; e < 4; e++) sacc[j][e] = 0.f;
            uint32_t kb[8];
            #pragma unroll
            for (int half = 0; half < 2; half++) {
                const int row = j * 8 + (lane & 7);
                const int chunk = half * 4 + (lane >> 3);
                ldsm_x4(base + sw128((uint32_t)(row * 128 + chunk * 16)), kb + half * 4);
            }
            #pragma unroll
            for (int kc = 0; kc < 4; kc++) {
                const int i0 = (kc >> 1) * 4 + (kc & 1) * 2;
                mma16816(sacc[j], qh[kc], kb[i0], kb[i0 + 1]);
            }
        }

        // ---- mask + exp (MUFU) + pack P ----
        uint32_t pf[4][4];
        const int kb = kt * 64;
        #pragma unroll
        for (int j = 0; j < 8; j++) {
            uint2 m0 = *(const uint2*)(mrow0 + kb + j * 8 + qc2);
            uint2 m1 = *(const uint2*)(mrow1 + kb + j * 8 + qc2);
            float p0 = m0.x ? ex2f(sacc[j][0] * SC) : 0.f;
            float p1 = m0.y ? ex2f(sacc[j][1] * SC) : 0.f;
            float p2 = m1.x ? ex2f(sacc[j][2] * SC) : 0.f;
            float p3 = m1.y ? ex2f(sacc[j][3] * SC) : 0.f;
            lsum0 += p0 + p1;
            lsum1 += p2 + p3;
            pf[j >> 1][(j & 1) * 2 + 0] = packh(p0, p1);
            pf[j >> 1][(j & 1) * 2 + 1] = packh(p2, p3);
        }

        // ---- ctx += P V ----
        #pragma unroll
        for (int kc = 0; kc < 4; kc++) {
            #pragma unroll
            for (int dp = 0; dp < 4; dp++) {
                const int row = kc * 16 + ((lane >> 3) & 1) * 8 + (lane & 7);
                const int chunk = dp * 2 + (lane >> 4);
                uint32_t vb[4];
                ldsm_x4t(base + 8192 + sw128((uint32_t)(row * 128 + chunk * 16)), vb);
                mma16816(ctx[dp*2],   pf[kc], vb[0], vb[1]);
                mma16816(ctx[dp*2+1], pf[kc], vb[2], vb[3]);
            }
        }
        if (kt + 2 < NT) load_tile(kt + 2);
    }

    // ---- normalize + write ctx (fp16) into [b, s, h*64+d] ----
    lsum0 += __shfl_xor_sync(0xffffffffu, lsum0, 1);
    lsum0 += __shfl_xor_sync(0xffffffffu, lsum0, 2);
    lsum1 += __shfl_xor_sync(0xffffffffu, lsum1, 1);
    lsum1 += __shfl_xor_sync(0xffffffffu, lsum1, 2);
    const float inv0 = (lsum0 > 0.f) ? 1.f / lsum0 : 0.f;
    const float inv1 = (lsum1 > 0.f) ? 1.f / lsum1 : 0.f;
    const int b = bh >> 4, h = bh & (NH - 1);
    const int s0 = q0 + w * 16 + r;
    const size_t base0 = ((size_t)b * SEQ + s0) * DM + h * 64;
    const size_t base1 = base0 + (size_t)8 * DM;
    #pragma unroll
    for (int j = 0; j < 8; j++) {
        const int d = j * 8 + qc2;
        *(__half2*)(g_ch + base0 + d) =
            __floats2half2_rn(ctx[j][0] * inv0, ctx[j][1] * inv0);
        *(__half2*)(g_ch + base1 + d) =
            __floats2half2_rn(ctx[j][2] * inv1, ctx[j][3] * inv1);
    }
}

// ---------------- launch ----------------
extern "C" void kernel_launch(void* const* d_in, const int* in_sizes, int n_in,
                              void* d_out, int out_size)
{
    const float* x  = (const float*)d_in[0];
    const uint32_t* maskw = (const uint32_t*)d_in[1];
    const float* Wq = (const float*)d_in[2];
    const float* bq = (const float*)d_in[3];
    const float* Wk = (const float*)d_in[4];
    const float* bk = (const float*)d_in[5];
    const float* Wv = (const float*)d_in[6];
    const float* bv = (const float*)d_in[7];
    const float* Wo = (const float*)d_in[8];
    const float* bo = (const float*)d_in[9];
    float* out = (float*)d_out;

    __half *xh, *ch;
    cudaGetSymbolAddress((void**)&xh, g_xh);
    cudaGetSymbolAddress((void**)&ch, g_ch);

    const int GEMM_SMEM = 3 * GSTG;   // 49152
    const int ATTN_SMEM = 3 * ASTG;   // 49152
    cudaFuncSetAttribute(gemm_qkv, cudaFuncAttributeMaxDynamicSharedMemorySize, GEMM_SMEM);
    cudaFuncSetAttribute(gemm_o,   cudaFuncAttributeMaxDynamicSharedMemorySize, GEMM_SMEM);
    cudaFuncSetAttribute(attn_tc,  cudaFuncAttributeMaxDynamicSharedMemorySize, ATTN_SMEM);

    const int nx4 = (int)((size_t)MTOT * DM / 4);
    const int nw4 = (int)((size_t)DM * DM / 4);
    conv_s<<<nx4/256, 256>>>((const float4*)x, (__half2*)xh, nx4);
    dim3 wgrid(nw4/256, 4);
    conv_w<<<wgrid, 256>>>((const float4*)Wq, (const float4*)Wk,
                           (const float4*)Wv, (const float4*)Wo, nw4);

    dim3 qkvgrid(DM / 128, MTOT / 128, 3);   // (8, 32, 3)
    gemm_qkv<<<qkvgrid, 256, GEMM_SMEM>>>(xh, bq, bk, bv);

    dim3 agrid(SEQ / 128, NB * NH);          // (16, 32)
    attn_tc<<<agrid, 256, ATTN_SMEM>>>(maskw);

    dim3 ogrid(DM / 128, MTOT / 128);        // (8, 32)
    gemm_o<<<ogrid, 256, GEMM_SMEM>>>(ch, bo, out);
}

// round 10
// speedup vs baseline: 9.0576x; 1.0021x over previous
#include <cuda_runtime.h>
#include <cuda_fp16.h>
#include <math.h>
#include <stdint.h>

#define NH   16
#define HD   64
#define NB   2
#define SEQ  2048
#define DM   1024
#define MTOT (NB*SEQ)

// ---------------- device scratch (allocation-free rule) ----------------
__device__ __align__(256) __half g_Qh[(size_t)NB*NH*SEQ*HD];
__device__ __align__(256) __half g_Kh[(size_t)NB*NH*SEQ*HD];
__device__ __align__(256) __half g_Vh[(size_t)NB*NH*SEQ*HD];
__device__ __align__(256) __half g_xh[(size_t)MTOT*DM];
__device__ __align__(256) __half g_ch[(size_t)MTOT*DM];
__device__ __align__(256) __half g_w4[4][(size_t)DM*DM];   // Wq, Wk, Wv, Wo fp16

// ---------------- helpers ----------------
__device__ __forceinline__ uint32_t smem_u32(const void* p) {
    uint32_t a;
    asm("{ .reg .u64 t; cvta.to.shared.u64 t, %1; cvt.u32.u64 %0, t; }" : "=r"(a) : "l"(p));
    return a;
}
__device__ __forceinline__ uint32_t sw128(uint32_t o) {   // 128B rows
    return o ^ (((o >> 7) & 7u) << 4);
}
__device__ __forceinline__ uint32_t sw64(uint32_t o) {    // 64B rows
    return o ^ (((o >> 7) & 3u) << 4);
}
__device__ __forceinline__ void cpasync16(uint32_t dst, const void* src) {
    asm volatile("cp.async.cg.shared.global [%0], [%1], 16;" :: "r"(dst), "l"(src));
}
__device__ __forceinline__ void cp_commit() {
    asm volatile("cp.async.commit_group;" ::: "memory");
}
__device__ __forceinline__ void cp_wait1() {
    asm volatile("cp.async.wait_group 1;" ::: "memory");
}
__device__ __forceinline__ void cp_wait0() {
    asm volatile("cp.async.wait_group 0;" ::: "memory");
}
__device__ __forceinline__ void ldsm_x4(uint32_t a, uint32_t* r) {
    asm volatile("ldmatrix.sync.aligned.m8n8.x4.shared.b16 {%0,%1,%2,%3}, [%4];"
                 : "=r"(r[0]), "=r"(r[1]), "=r"(r[2]), "=r"(r[3]) : "r"(a));
}
__device__ __forceinline__ void ldsm_x4t(uint32_t a, uint32_t* r) {
    asm volatile("ldmatrix.sync.aligned.m8n8.x4.trans.shared.b16 {%0,%1,%2,%3}, [%4];"
                 : "=r"(r[0]), "=r"(r[1]), "=r"(r[2]), "=r"(r[3]) : "r"(a));
}
__device__ __forceinline__ void mma16816(float* c, const uint32_t* a,
                                         uint32_t b0, uint32_t b1) {
    asm volatile(
        "mma.sync.aligned.m16n8k16.row.col.f32.f16.f16.f32 "
        "{%0,%1,%2,%3}, {%4,%5,%6,%7}, {%8,%9}, {%0,%1,%2,%3};"
        : "+f"(c[0]), "+f"(c[1]), "+f"(c[2]), "+f"(c[3])
        : "r"(a[0]), "r"(a[1]), "r"(a[2]), "r"(a[3]), "r"(b0), "r"(b1));
}
__device__ __forceinline__ float ex2f(float e) {
    float r;
    asm("ex2.approx.f32 %0, %1;" : "=f"(r) : "f"(e));
    return r;
}
__device__ __forceinline__ uint32_t packh(float lo, float hi) {
    __half2 h = __floats2half2_rn(lo, hi);
    return *(uint32_t*)&h;
}

// ---------------- conversions fp32 -> fp16 ----------------
__global__ __launch_bounds__(256) void conv_s(const float4* __restrict__ src,
                                              __half2* __restrict__ dst, int n4) {
    int i = blockIdx.x * 256 + threadIdx.x;
    if (i >= n4) return;
    float4 v = src[i];
    dst[2*i]   = __floats2half2_rn(v.x, v.y);
    dst[2*i+1] = __floats2half2_rn(v.z, v.w);
}
__global__ __launch_bounds__(256) void conv_w(const float4* __restrict__ w0,
                                              const float4* __restrict__ w1,
                                              const float4* __restrict__ w2,
                                              const float4* __restrict__ w3,
                                              int n4) {
    int i = blockIdx.x * 256 + threadIdx.x;
    if (i >= n4) return;
    const int s = blockIdx.y;
    const float4* src = (s == 0) ? w0 : (s == 1) ? w1 : (s == 2) ? w2 : w3;
    __half2* dst = (__half2*)g_w4[s];
    float4 v = src[i];
    dst[2*i]   = __floats2half2_rn(v.x, v.y);
    dst[2*i+1] = __floats2half2_rn(v.z, v.w);
}

// ---------------- shared GEMM mainloop (CTA 128x128, BK=32, 3-stage) ------
#define GSTG 16384   // stage stride: A 8K + B 8K

struct GemmCore {
    uint32_t sb;
    int tid, wid, lid, wm, wn, bm, bn;
    float acc[2][8][4];

    __device__ __forceinline__ void init(uint32_t sb_, int bm_, int bn_) {
        sb = sb_; tid = threadIdx.x; wid = tid >> 5; lid = tid & 31;
        wm = wid & 3; wn = wid >> 2; bm = bm_; bn = bn_;
        #pragma unroll
        for (int mi = 0; mi < 2; mi++)
            #pragma unroll
            for (int ni = 0; ni < 8; ni++)
                #pragma unroll
                for (int e = 0; e < 4; e++) acc[mi][ni][e] = 0.f;
    }
    __device__ __forceinline__ void load_stage(const __half* A_, const __half* B_,
                                               int c) {
        const uint32_t base = sb + (uint32_t)(c % 3) * GSTG;
        #pragma unroll
        for (int p = 0; p < 2; p++) {
            const int id = tid + p * 256;
            const int row = id >> 2, ch = id & 3;
            const uint32_t so = sw64((uint32_t)(row * 64 + ch * 16));
            const size_t ga = (size_t)(bm + row) * (DM / 8) + c * 4 + ch;
            const size_t gb = (size_t)(bn + row) * (DM / 8) + c * 4 + ch;
            cpasync16(base + so,        (const uint4*)A_ + ga);
            cpasync16(base + 8192 + so, (const uint4*)B_ + gb);
        }
        cp_commit();
    }
    __device__ __forceinline__ void mainloop(const __half* A_, const __half* B_) {
        const int NIT = DM / 32;
        load_stage(A_, B_, 0);
        load_stage(A_, B_, 1);
        for (int c = 0; c < NIT; c++) {
            if (c == NIT - 1) cp_wait0(); else cp_wait1();
            __syncthreads();
            const uint32_t base = sb + (uint32_t)(c % 3) * GSTG;
            #pragma unroll
            for (int ks = 0; ks < 2; ks++) {
                uint32_t ah[2][4];
                #pragma unroll
                for (int mi = 0; mi < 2; mi++) {
                    const int row = wm * 32 + mi * 16 + (lid & 15);
                    const int colb = (ks * 16 + (lid >> 4) * 8) * 2;
                    ldsm_x4(base + sw64((uint32_t)(row * 64 + colb)), ah[mi]);
                }
                uint32_t bh[8][2];
                #pragma unroll
                for (int nj = 0; nj < 4; nj++) {
                    const int row = wn * 64 + nj * 16 + ((lid >> 4) << 3) + (lid & 7);
                    const int colb = (ks * 16 + ((lid >> 3) & 1) * 8) * 2;
                    uint32_t t[4];
                    ldsm_x4(base + 8192 + sw64((uint32_t)(row * 64 + colb)), t);
                    bh[nj*2][0] = t[0]; bh[nj*2][1] = t[1];
                    bh[nj*2+1][0] = t[2]; bh[nj*2+1][1] = t[3];
                }
                #pragma unroll
                for (int mi = 0; mi < 2; mi++)
                    #pragma unroll
                    for (int ni = 0; ni < 8; ni++)
                        mma16816(acc[mi][ni], ah[mi], bh[ni][0], bh[ni][1]);
            }
            if (c + 2 < NIT) load_stage(A_, B_, c + 2);
        }
    }
};

// QKV fused: blockIdx.z selects weight / bias / output. Output half [b,h,s,d].
__global__ __launch_bounds__(256, 2)
void gemm_qkv(const __half* __restrict__ A_,
              const float* __restrict__ bq, const float* __restrict__ bk,
              const float* __restrict__ bv)
{
    extern __shared__ char smb[];
    const int z = blockIdx.z;
    const __half* B_ = g_w4[z];
    const float* bias = (z == 0) ? bq : (z == 1) ? bk : bv;
    __half* OutH = (z == 0) ? g_Qh : (z == 1) ? g_Kh : g_Vh;

    GemmCore g;
    g.init(smem_u32(smb), blockIdx.y * 128, blockIdx.x * 128);
    g.mainloop(A_, B_);

    const int qr = g.lid >> 2, qc = g.lid & 3;
    #pragma unroll
    for (int mi = 0; mi < 2; mi++) {
        #pragma unroll
        for (int half = 0; half < 2; half++) {
            const int m = g.bm + g.wm * 32 + mi * 16 + half * 8 + qr;
            const int n0 = g.bn + g.wn * 64;
            const int b = m >> 11, s = m & (SEQ - 1);
            const int h = n0 >> 6;
            const size_t base = ((size_t)(b * NH + h) * SEQ + s) * HD;
            #pragma unroll
            for (int ni = 0; ni < 8; ni++) {
                const int nloc = ni * 8 + qc * 2;
                const int ng = n0 + nloc;
                *(__half2*)(OutH + base + nloc) = __floats2half2_rn(
                    g.acc[mi][ni][half*2+0] + bias[ng],
                    g.acc[mi][ni][half*2+1] + bias[ng + 1]);
            }
        }
    }
}

// Output GEMM: fp32 row-major into d_out
__global__ __launch_bounds__(256, 2)
void gemm_o(const __half* __restrict__ A_, const float* __restrict__ bias,
            float* __restrict__ Out)
{
    extern __shared__ char smb[];
    GemmCore g;
    g.init(smem_u32(smb), blockIdx.y * 128, blockIdx.x * 128);
    g.mainloop(A_, g_w4[3]);

    const int qr = g.lid >> 2, qc = g.lid & 3;
    #pragma unroll
    for (int mi = 0; mi < 2; mi++) {
        #pragma unroll
        for (int half = 0; half < 2; half++) {
            const int m = g.bm + g.wm * 32 + mi * 16 + half * 8 + qr;
            const int n0 = g.bn + g.wn * 64;
            float* dst = Out + (size_t)m * DM;
            #pragma unroll
            for (int ni = 0; ni < 8; ni++) {
                const int ng = n0 + ni * 8 + qc * 2;
                float2 o;
                o.x = g.acc[mi][ni][half*2+0] + bias[ng];
                o.y = g.acc[mi][ni][half*2+1] + bias[ng + 1];
                *(float2*)(dst + ng) = o;
            }
        }
    }
}

// ---------------- fp16 tensor-core flash attention ----------------
// grid (SEQ/128, NB*NH), 256 threads, 2 CTAs/SM. Q in regs.
// Stage = K 8K + V 8K + mask 128x272B; 2-stage cp.async pipeline that
// ALSO carries the mask slab (128 rows x 64 words, coalesced 128B lines).
// Softmax reads mask from smem (LDS.64, padded rows).
#define MSTRIDE 272                       // 64 words + 16B pad (bank spread)
#define AMOFF   16384                     // mask offset within stage
#define ASTG    (16384 + 128*MSTRIDE)     // 51200
__global__ __launch_bounds__(256, 2) void attn_tc(const uint32_t* __restrict__ maskw)
{
    extern __shared__ char smb[];
    const uint32_t sb = smem_u32(smb);
    const int tid = threadIdx.x, w = tid >> 5, lane = tid & 31;
    const int bh = blockIdx.y, q0 = blockIdx.x * 128;
    const int r = lane >> 2, qc2 = (lane & 3) * 2;
    const float SC = 0.125f * 1.44269504f;
    const int NT = SEQ / 64;

    // ---- stage Q tile, pull fragments ----
    {
        const __half* Q = g_Qh + ((size_t)bh * SEQ + q0) * HD;
        const int row = tid >> 1, cg = (tid & 1) * 4;
        #pragma unroll
        for (int c = 0; c < 4; c++) {
            const uint32_t off = sw128((uint32_t)(row * 128 + (cg + c) * 16));
            *(uint4*)(smb + off) = ((const uint4*)(Q + row * HD))[cg + c];
        }
    }
    __syncthreads();
    uint32_t qh[4][4];
    {
        const int row = w * 16 + ((lane >> 3) & 1) * 8 + (lane & 7);
        #pragma unroll
        for (int kc = 0; kc < 4; kc++) {
            const int chunk = kc * 2 + (lane >> 4);
            ldsm_x4(sb + sw128((uint32_t)(row * 128 + chunk * 16)), qh[kc]);
        }
    }
    __syncthreads();

    float ctx[8][4];
    #pragma unroll
    for (int j = 0; j < 8; j++)
        #pragma unroll
        for (int e = 0; e < 4; e++) ctx[j][e] = 0.f;
    float lsum0 = 0.f, lsum1 = 0.f;

    const __half* Kp = g_Kh + (size_t)bh * SEQ * HD;
    const __half* Vp = g_Vh + (size_t)bh * SEQ * HD;
    const uint32_t* Mbase = maskw + ((size_t)bh * SEQ + q0) * SEQ;

    // tile loader: K/V (8 uint4 rows each, split over threads) + mask slab
    auto load_tile = [&](int kt) {
        const uint32_t stg = sb + (uint32_t)(kt & 1) * ASTG;
        {   // K/V: 128 rows total, 2 threads/row, 4 chunks each
            const int arr = tid >> 7;             // 0 = K, 1 = V
            const int row = (tid >> 1) & 63;
            const int cg  = (tid & 1) * 4;
            const __half* src = (arr == 0 ? Kp : Vp) + ((size_t)(kt * 64 + row)) * HD;
            const uint32_t dstb = stg + arr * 8192;
            #pragma unroll
            for (int c = 0; c < 4; c++) {
                cpasync16(dstb + sw128((uint32_t)(row * 128 + (cg + c) * 16)),
                          (const uint4*)src + cg + c);
            }
        }
        {   // mask: 128 rows x 256B, coalesced (16 threads cover one row)
            #pragma unroll
            for (int i = 0; i < 8; i++) {
                const int id = i * 256 + tid;
                const int row = id >> 4, ch = id & 15;
                cpasync16(stg + AMOFF + (uint32_t)(row * MSTRIDE + ch * 16),
                          Mbase + (size_t)row * SEQ + kt * 64 + ch * 4);
            }
        }
        cp_commit();
    };

    load_tile(0);

    for (int kt = 0; kt < NT; kt++) {
        cp_wait0();
        __syncthreads();
        if (kt + 1 < NT) load_tile(kt + 1);   // overlaps with compute below
        const uint32_t base = sb + (uint32_t)(kt & 1) * ASTG;

        // ---- S = Q K^T ----
        float sacc[8][4];
        #pragma unroll
        for (int j = 0; j < 8; j++) {
            #pragma unroll
            for (int e = 0; e < 4; e++) sacc[j][e] = 0.f;
            uint32_t kb[8];
            #pragma unroll
            for (int half = 0; half < 2; half++) {
                const int row = j * 8 + (lane & 7);
                const int chunk = half * 4 + (lane >> 3);
                ldsm_x4(base + sw128((uint32_t)(row * 128 + chunk * 16)), kb + half * 4);
            }
            #pragma unroll
            for (int kc = 0; kc < 4; kc++) {
                const int i0 = (kc >> 1) * 4 + (kc & 1) * 2;
                mma16816(sacc[j], qh[kc], kb[i0], kb[i0 + 1]);
            }
        }

        // ---- mask (from smem) + exp (MUFU) + pack P ----
        uint32_t pf[4][4];
        const char* mrow0 = smb + (kt & 1) * ASTG + AMOFF + (w * 16 + r) * MSTRIDE;
        const char* mrow1 = mrow0 + 8 * MSTRIDE;
        #pragma unroll
        for (int j = 0; j < 8; j++) {
            uint2 m0 = *(const uint2*)(mrow0 + (j * 8 + qc2) * 4);
            uint2 m1 = *(const uint2*)(mrow1 + (j * 8 + qc2) * 4);
            float p0 = m0.x ? ex2f(sacc[j][0] * SC) : 0.f;
            float p1 = m0.y ? ex2f(sacc[j][1] * SC) : 0.f;
            float p2 = m1.x ? ex2f(sacc[j][2] * SC) : 0.f;
            float p3 = m1.y ? ex2f(sacc[j][3] * SC) : 0.f;
            lsum0 += p0 + p1;
            lsum1 += p2 + p3;
            pf[j >> 1][(j & 1) * 2 + 0] = packh(p0, p1);
            pf[j >> 1][(j & 1) * 2 + 1] = packh(p2, p3);
        }

        // ---- ctx += P V ----
        #pragma unroll
        for (int kc = 0; kc < 4; kc++) {
            #pragma unroll
            for (int dp = 0; dp < 4; dp++) {
                const int row = kc * 16 + ((lane >> 3) & 1) * 8 + (lane & 7);
                const int chunk = dp * 2 + (lane >> 4);
                uint32_t vb[4];
                ldsm_x4t(base + 8192 + sw128((uint32_t)(row * 128 + chunk * 16)), vb);
                mma16816(ctx[dp*2],   pf[kc], vb[0], vb[1]);
                mma16816(ctx[dp*2+1], pf[kc], vb[2], vb[3]);
            }
        }
    }

    // ---- normalize + write ctx (fp16) into [b, s, h*64+d] ----
    lsum0 += __shfl_xor_sync(0xffffffffu, lsum0, 1);
    lsum0 += __shfl_xor_sync(0xffffffffu, lsum0, 2);
    lsum1 += __shfl_xor_sync(0xffffffffu, lsum1, 1);
    lsum1 += __shfl_xor_sync(0xffffffffu, lsum1, 2);
    const float inv0 = (lsum0 > 0.f) ? 1.f / lsum0 : 0.f;
    const float inv1 = (lsum1 > 0.f) ? 1.f / lsum1 : 0.f;
    const int b = bh >> 4, h = bh & (NH - 1);
    const int s0 = q0 + w * 16 + r;
    const size_t base0 = ((size_t)b * SEQ + s0) * DM + h * 64;
    const size_t base1 = base0 + (size_t)8 * DM;
    #pragma unroll
    for (int j = 0; j < 8; j++) {
        const int d = j * 8 + qc2;
        *(__half2*)(g_ch + base0 + d) =
            __floats2half2_rn(ctx[j][0] * inv0, ctx[j][1] * inv0);
        *(__half2*)(g_ch + base1 + d) =
            __floats2half2_rn(ctx[j][2] * inv1, ctx[j][3] * inv1);
    }
}

// ---------------- launch ----------------
extern "C" void kernel_launch(void* const* d_in, const int* in_sizes, int n_in,
                              void* d_out, int out_size)
{
    const float* x  = (const float*)d_in[0];
    const uint32_t* maskw = (const uint32_t*)d_in[1];
    const float* Wq = (const float*)d_in[2];
    const float* bq = (const float*)d_in[3];
    const float* Wk = (const float*)d_in[4];
    const float* bk = (const float*)d_in[5];
    const float* Wv = (const float*)d_in[6];
    const float* bv = (const float*)d_in[7];
    const float* Wo = (const float*)d_in[8];
    const float* bo = (const float*)d_in[9];
    float* out = (float*)d_out;

    __half *xh, *ch;
    cudaGetSymbolAddress((void**)&xh, g_xh);
    cudaGetSymbolAddress((void**)&ch, g_ch);

    const int GEMM_SMEM = 3 * GSTG;   // 49152
    const int ATTN_SMEM = 2 * ASTG;   // 102400
    cudaFuncSetAttribute(gemm_qkv, cudaFuncAttributeMaxDynamicSharedMemorySize, GEMM_SMEM);
    cudaFuncSetAttribute(gemm_o,   cudaFuncAttributeMaxDynamicSharedMemorySize, GEMM_SMEM);
    cudaFuncSetAttribute(attn_tc,  cudaFuncAttributeMaxDynamicSharedMemorySize, ATTN_SMEM);

    const int nx4 = (int)((size_t)MTOT * DM / 4);
    const int nw4 = (int)((size_t)DM * DM / 4);
    conv_s<<<nx4/256, 256>>>((const float4*)x, (__half2*)xh, nx4);
    dim3 wgrid(nw4/256, 4);
    conv_w<<<wgrid, 256>>>((const float4*)Wq, (const float4*)Wk,
                           (const float4*)Wv, (const float4*)Wo, nw4);

    dim3 qkvgrid(DM / 128, MTOT / 128, 3);   // (8, 32, 3)
    gemm_qkv<<<qkvgrid, 256, GEMM_SMEM>>>(xh, bq, bk, bv);

    dim3 agrid(SEQ / 128, NB * NH);          // (16, 32)
    attn_tc<<<agrid, 256, ATTN_SMEM>>>(maskw);

    dim3 ogrid(DM / 128, MTOT / 128);        // (8, 32)
    gemm_o<<<ogrid, 256, GEMM_SMEM>>>(ch, bo, out);
}